// round 1
// baseline (speedup 1.0000x reference)
#include <cuda_runtime.h>
#include <cuda_bf16.h>
#include <math_constants.h>

// Problem constants
// D=1024, H=16, M=1024, K=4, ST=1, P=0, HD=64, VD=16
// x: (2,1024,1024)  -> Q = x @ Wq^T + bq : (2048,1024)
// per position p (2048): 16 heads, logits(1024) = qh(64)·Wk^T, softmax/8, vals(16)=att·Wv^T+bv
// V[b,p, h*16+v] (2048x256)
// out[b,w,d] = sum_j V[b, w*256+j]*Wh[d,j] + bh[d], w in [0,1021)

__device__ float g_Q[2048 * 1024];   // 8 MB scratch
__device__ float g_V[2048 * 256];    // 2 MB scratch

// ---------------------------------------------------------------------------
// Tiled fp32 SGEMM (NT): C[r][c] = sum_k A[r][k]*B[c][k] + bias[c]
// BM=BN=128, BK=8, 256 threads, 8x8 per thread in 2x2 strips of 4.
// A row stride = lda (supports overlapping-window A with lda=256).
// N and K must be multiples of 128 / 8 (true for all our calls). M guarded.
// ---------------------------------------------------------------------------
__global__ __launch_bounds__(256)
void sgemm_nt(const float* __restrict__ A, long aBatch, int lda,
              const float* __restrict__ B, int ldb,
              const float* __restrict__ bias,
              float* __restrict__ C, long cBatch, int ldc,
              int M, int N, int K)
{
    __shared__ float As[8][128];
    __shared__ float Bs[8][128];

    const int tid = threadIdx.x;
    const int tx = tid & 15;        // 0..15 (cols)
    const int ty = tid >> 4;        // 0..15 (rows)
    const int row0 = blockIdx.y * 128;
    const int col0 = blockIdx.x * 128;

    const float* Ab = A + (long)blockIdx.z * aBatch;
    float* Cb = C + (long)blockIdx.z * cBatch;

    const int lrow = tid >> 1;          // 0..127
    const int lsub = (tid & 1) * 4;     // 0 or 4
    const bool aValid = (row0 + lrow) < M;
    const float* aPtr = Ab + (long)(row0 + lrow) * lda + lsub;
    const float* bPtr = B + (long)(col0 + lrow) * ldb + lsub;

    float acc[8][8] = {};

    for (int k0 = 0; k0 < K; k0 += 8) {
        float4 av = aValid ? *(const float4*)(aPtr + k0) : make_float4(0.f, 0.f, 0.f, 0.f);
        float4 bv = *(const float4*)(bPtr + k0);
        __syncthreads();
        As[lsub + 0][lrow] = av.x;
        As[lsub + 1][lrow] = av.y;
        As[lsub + 2][lrow] = av.z;
        As[lsub + 3][lrow] = av.w;
        Bs[lsub + 0][lrow] = bv.x;
        Bs[lsub + 1][lrow] = bv.y;
        Bs[lsub + 2][lrow] = bv.z;
        Bs[lsub + 3][lrow] = bv.w;
        __syncthreads();

        #pragma unroll
        for (int kk = 0; kk < 8; kk++) {
            float4 a0 = *(const float4*)&As[kk][ty * 4];
            float4 a1 = *(const float4*)&As[kk][64 + ty * 4];
            float4 b0 = *(const float4*)&Bs[kk][tx * 4];
            float4 b1 = *(const float4*)&Bs[kk][64 + tx * 4];
            float ar[8] = {a0.x, a0.y, a0.z, a0.w, a1.x, a1.y, a1.z, a1.w};
            float br[8] = {b0.x, b0.y, b0.z, b0.w, b1.x, b1.y, b1.z, b1.w};
            #pragma unroll
            for (int i = 0; i < 8; i++)
                #pragma unroll
                for (int j = 0; j < 8; j++)
                    acc[i][j] += ar[i] * br[j];
        }
    }

    // bias for this thread's two column strips
    float4 bia0 = *(const float4*)&bias[col0 + tx * 4];
    float4 bia1 = *(const float4*)&bias[col0 + 64 + tx * 4];
    const float bb[8] = {bia0.x, bia0.y, bia0.z, bia0.w, bia1.x, bia1.y, bia1.z, bia1.w};

    #pragma unroll
    for (int i = 0; i < 8; i++) {
        int r = row0 + ((i < 4) ? (ty * 4 + i) : (64 + ty * 4 + (i - 4)));
        if (r >= M) continue;
        float4 v0 = make_float4(acc[i][0] + bb[0], acc[i][1] + bb[1],
                                acc[i][2] + bb[2], acc[i][3] + bb[3]);
        float4 v1 = make_float4(acc[i][4] + bb[4], acc[i][5] + bb[5],
                                acc[i][6] + bb[6], acc[i][7] + bb[7]);
        *(float4*)&Cb[(long)r * ldc + col0 + tx * 4] = v0;
        *(float4*)&Cb[(long)r * ldc + col0 + 64 + tx * 4] = v1;
    }
}

// ---------------------------------------------------------------------------
// Fused per-position attention: one CTA per position (2048 CTAs, 256 threads).
// smem: q(1024f) | probs(16x1024f) | WvT(1024x20f padded)
// ---------------------------------------------------------------------------
#define ATTN_SMEM_FLOATS (1024 + 16 * 1024 + 1024 * 20)
#define ATTN_SMEM_BYTES  (ATTN_SMEM_FLOATS * 4)

__global__ __launch_bounds__(256)
void attn_kernel(const float* __restrict__ Q, const float* __restrict__ Wk,
                 const float* __restrict__ bk, const float* __restrict__ Wv,
                 const float* __restrict__ bv, float* __restrict__ V)
{
    extern __shared__ float sm[];
    float* q_s   = sm;                  // 1024
    float* probs = sm + 1024;           // 16*1024
    float* wvT   = sm + 1024 + 16384;   // 1024*20 (16 used, pad 20 for bank-safe float4)

    const int tid = threadIdx.x;
    const int pos = blockIdx.x;         // b*1024 + p

    // load q row (coalesced, 4 floats/thread)
    ((float4*)q_s)[tid] = ((const float4*)(Q + (long)pos * 1024))[tid];

    // load Wv transposed: wvT[m*20 + v] = Wv[v*1024 + m]
    for (int i = tid; i < 16384; i += 256) {
        int v = i >> 10, m = i & 1023;
        wvT[m * 20 + v] = Wv[i];
    }
    __syncthreads();

    // ---- logits: this thread owns m_j = tid + 256*j (j=0..3), all 16 heads ----
    float acc[16][4];
    #pragma unroll
    for (int h = 0; h < 16; h++)
        #pragma unroll
        for (int j = 0; j < 4; j++) acc[h][j] = 0.f;

    const float4* Wk4 = (const float4*)Wk;   // 1024 rows x 16 float4
    #pragma unroll 2
    for (int e0 = 0; e0 < 64; e0 += 4) {
        float wv[4][4];
        #pragma unroll
        for (int j = 0; j < 4; j++)
            *(float4*)&wv[j][0] = Wk4[(tid + 256 * j) * 16 + (e0 >> 2)];
        #pragma unroll
        for (int c = 0; c < 4; c++) {
            #pragma unroll
            for (int h = 0; h < 16; h++) {
                float qv = q_s[h * 64 + e0 + c];
                #pragma unroll
                for (int j = 0; j < 4; j++)
                    acc[h][j] += qv * wv[j][c];
            }
        }
    }
    #pragma unroll
    for (int j = 0; j < 4; j++) {
        int m = tid + 256 * j;
        float bkm = bk[m];
        #pragma unroll
        for (int h = 0; h < 16; h++)
            probs[h * 1024 + m] = (acc[h][j] + bkm) * 0.125f;  // 1/sqrt(64)
    }
    __syncthreads();

    // ---- softmax over m per head: warp w handles heads w and w+8 ----
    const int warp = tid >> 5, lane = tid & 31;
    for (int h = warp; h < 16; h += 8) {
        float* row = probs + h * 1024;
        float mx = -CUDART_INF_F;
        for (int i = lane; i < 1024; i += 32) mx = fmaxf(mx, row[i]);
        #pragma unroll
        for (int off = 16; off; off >>= 1)
            mx = fmaxf(mx, __shfl_xor_sync(0xffffffffu, mx, off));
        float sum = 0.f;
        for (int i = lane; i < 1024; i += 32) {
            float e = __expf(row[i] - mx);
            row[i] = e;
            sum += e;
        }
        #pragma unroll
        for (int off = 16; off; off >>= 1)
            sum += __shfl_xor_sync(0xffffffffu, sum, off);
        float inv = 1.f / sum;
        for (int i = lane; i < 1024; i += 32) row[i] *= inv;
    }
    __syncthreads();

    // ---- vals: thread (h = tid/16, s = tid%16) accumulates all 16 v over m=s::16 ----
    {
        const int h = tid >> 4, s = tid & 15;
        float a[16];
        #pragma unroll
        for (int v = 0; v < 16; v++) a[v] = 0.f;
        const float* prow = probs + h * 1024;
        #pragma unroll 4
        for (int m = s; m < 1024; m += 16) {
            float p = prow[m];
            const float4* wr = (const float4*)&wvT[m * 20];
            float4 w0 = wr[0], w1 = wr[1], w2 = wr[2], w3 = wr[3];
            a[0]  += p * w0.x; a[1]  += p * w0.y; a[2]  += p * w0.z; a[3]  += p * w0.w;
            a[4]  += p * w1.x; a[5]  += p * w1.y; a[6]  += p * w1.z; a[7]  += p * w1.w;
            a[8]  += p * w2.x; a[9]  += p * w2.y; a[10] += p * w2.z; a[11] += p * w2.w;
            a[12] += p * w3.x; a[13] += p * w3.y; a[14] += p * w3.z; a[15] += p * w3.w;
        }
        // reduce over the 16 lanes of this head group (half-warp segments)
        #pragma unroll
        for (int off = 8; off; off >>= 1)
            #pragma unroll
            for (int v = 0; v < 16; v++)
                a[v] += __shfl_down_sync(0xffffffffu, a[v], off, 16);
        if (s == 0) {
            float* outp = V + (long)pos * 256 + h * 16;
            #pragma unroll
            for (int v = 0; v < 16; v++) outp[v] = a[v] + bv[v];
        }
    }
}

// ---------------------------------------------------------------------------
extern "C" void kernel_launch(void* const* d_in, const int* in_sizes, int n_in,
                              void* d_out, int out_size)
{
    const float* x  = (const float*)d_in[0];
    const float* Wq = (const float*)d_in[1];
    const float* bq = (const float*)d_in[2];
    const float* Wk = (const float*)d_in[3];
    const float* bk = (const float*)d_in[4];
    const float* Wv = (const float*)d_in[5];
    const float* bv = (const float*)d_in[6];
    const float* Wh = (const float*)d_in[7];
    const float* bh = (const float*)d_in[8];
    float* out = (float*)d_out;

    float *Qs = nullptr, *Vs = nullptr;
    cudaGetSymbolAddress((void**)&Qs, g_Q);
    cudaGetSymbolAddress((void**)&Vs, g_V);

    cudaFuncSetAttribute(attn_kernel, cudaFuncAttributeMaxDynamicSharedMemorySize,
                         ATTN_SMEM_BYTES);

    // Stage 1: Q = x @ Wq^T + bq   (2048 x 1024 x 1024)
    sgemm_nt<<<dim3(8, 16, 1), 256>>>(x, 0, 1024, Wq, 1024, bq,
                                      Qs, 0, 1024, 2048, 1024, 1024);

    // Stage 2: per-position attention -> V (2048 x 256)
    attn_kernel<<<2048, 256, ATTN_SMEM_BYTES>>>(Qs, Wk, bk, Wv, bv, Vs);

    // Stage 3: out[b,w,:] = V[b, w*256 : w*256+1024] @ Wh^T + bh  (overlapping rows, lda=256)
    sgemm_nt<<<dim3(8, 8, 2), 256>>>(Vs, 262144, 256, Wh, 1024, bh,
                                     out, 1021L * 1024, 1024, 1021, 1024, 1024);
}

// round 3
// speedup vs baseline: 5.6801x; 5.6801x over previous
#include <cuda_runtime.h>
#include <cuda_fp16.h>
#include <cstdint>

// D=1024, H=16, M=1024, K=4, ST=1, HD=64, VD=16
// Pipeline (all tensor-core fp16 mma, fp32 accum):
//   Q = x @ Wq^T + bq                         (2048 x 1024 x 1024)
//   Qh = reshape(Q) -> (32768 x 64) rows = (pos,head)
//   flash: S = Qh @ Wk^T (+bk)/8 ; att=softmax ; V = att @ Wv^T + bv  (32768x16)
//   out[b,w,:] = V[b, w*256 : w*256+1024] @ Wh^T + bh   (overlap => lda=256)

__device__ __half g_x16 [2048 * 1024];
__device__ __half g_Wq16[1024 * 1024];
__device__ __half g_Wk16[1024 * 64];
__device__ __half g_Wv16[16 * 1024];
__device__ __half g_Wh16[1024 * 1024];
__device__ __half g_Q16 [2048 * 1024];
__device__ __half g_V16 [2048 * 256 + 2048];   // +pad: stage-3 tail rows overrun

// ---------------------------------------------------------------------------
__global__ void cvt_f2h(const float4* __restrict__ in, __half2* __restrict__ out, int n4)
{
    int i = blockIdx.x * blockDim.x + threadIdx.x;
    if (i < n4) {
        float4 v = in[i];
        out[2 * i]     = __floats2half2_rn(v.x, v.y);
        out[2 * i + 1] = __floats2half2_rn(v.z, v.w);
    }
}

// ---------------------------------------------------------------------------
__device__ __forceinline__ void mma_f16(float* c, const uint32_t* a, uint32_t b0, uint32_t b1)
{
    asm volatile(
        "mma.sync.aligned.m16n8k16.row.col.f32.f16.f16.f32 "
        "{%0,%1,%2,%3}, {%4,%5,%6,%7}, {%8,%9}, {%0,%1,%2,%3};\n"
        : "+f"(c[0]), "+f"(c[1]), "+f"(c[2]), "+f"(c[3])
        : "r"(a[0]), "r"(a[1]), "r"(a[2]), "r"(a[3]), "r"(b0), "r"(b1));
}

// ---------------------------------------------------------------------------
// HGEMM NT: C[r][c] = sum_k A[r][k]*B[c][k] + bias[c]
// BM=BN=128, BK=32, 256 threads (8 warps, warp tile 32x64).
// smem stride 40 halves (=20 words == 4 mod 32 per 8-row group -> conflict-free frags)
// ---------------------------------------------------------------------------
template <bool HALF_OUT>
__global__ __launch_bounds__(256)
void hgemm_nt(const __half* __restrict__ A, long aBatch, int lda,
              const __half* __restrict__ B,
              const float* __restrict__ bias,
              void* __restrict__ Cv, long cBatch, int ldc,
              int M, int N, int K)
{
    __shared__ __half As[128][40];
    __shared__ __half Bs[128][40];

    const int tid = threadIdx.x;
    const int warp = tid >> 5, lane = tid & 31;
    const int qr = lane >> 2, grp = lane & 3;
    const int wr = (warp & 3) * 32;         // warp row in tile
    const int wc = (warp >> 2) * 64;        // warp col in tile
    const int row0 = blockIdx.y * 128;
    const int col0 = blockIdx.x * 128;

    const __half* Ab = A + (long)blockIdx.z * aBatch;

    float acc[16][4] = {};                  // [mi*8+nj][4]

    for (int k0 = 0; k0 < K; k0 += 32) {
        // load tiles: 512 float4 each, 2 per thread
        #pragma unroll
        for (int i = 0; i < 2; i++) {
            int v = tid + 256 * i;
            int r = v >> 2, c8 = (v & 3) * 8;
            *(float4*)&As[r][c8] = *(const float4*)&Ab[(long)(row0 + r) * lda + k0 + c8];
            *(float4*)&Bs[r][c8] = *(const float4*)&B[(long)(col0 + r) * 1024 + k0 + c8];
        }
        __syncthreads();

        #pragma unroll
        for (int kk = 0; kk < 32; kk += 16) {
            uint32_t af[2][4];
            #pragma unroll
            for (int mi = 0; mi < 2; mi++) {
                int r = wr + mi * 16 + qr;
                af[mi][0] = *(const uint32_t*)&As[r][kk + grp * 2];
                af[mi][1] = *(const uint32_t*)&As[r + 8][kk + grp * 2];
                af[mi][2] = *(const uint32_t*)&As[r][kk + 8 + grp * 2];
                af[mi][3] = *(const uint32_t*)&As[r + 8][kk + 8 + grp * 2];
            }
            #pragma unroll
            for (int nj = 0; nj < 8; nj++) {
                int n = wc + nj * 8 + qr;
                uint32_t b0 = *(const uint32_t*)&Bs[n][kk + grp * 2];
                uint32_t b1 = *(const uint32_t*)&Bs[n][kk + 8 + grp * 2];
                mma_f16(acc[0 * 8 + nj], af[0], b0, b1);
                mma_f16(acc[1 * 8 + nj], af[1], b0, b1);
            }
        }
        __syncthreads();
    }

    // epilogue
    #pragma unroll
    for (int mi = 0; mi < 2; mi++) {
        #pragma unroll
        for (int nj = 0; nj < 8; nj++) {
            float* c = acc[mi * 8 + nj];
            int col = col0 + wc + nj * 8 + grp * 2;
            float b0 = bias[col], b1 = bias[col + 1];
            int rA = row0 + wr + mi * 16 + qr;
            int rB = rA + 8;
            if (HALF_OUT) {
                __half* C = (__half*)Cv + (long)blockIdx.z * cBatch;
                if (rA < M) *(__half2*)&C[(long)rA * ldc + col] = __floats2half2_rn(c[0] + b0, c[1] + b1);
                if (rB < M) *(__half2*)&C[(long)rB * ldc + col] = __floats2half2_rn(c[2] + b0, c[3] + b1);
            } else {
                float* C = (float*)Cv + (long)blockIdx.z * cBatch;
                if (rA < M) *(float2*)&C[(long)rA * ldc + col] = make_float2(c[0] + b0, c[1] + b1);
                if (rB < M) *(float2*)&C[(long)rB * ldc + col] = make_float2(c[2] + b0, c[3] + b1);
            }
        }
    }
}

// ---------------------------------------------------------------------------
// Flash attention: rows = Qh (32768 x 64), K = Wk (1024 x 64), V = Wv^T (1024 x 16)
// 128 rows/CTA (256 CTAs), 8 warps x 16 rows, online softmax over 8 m-chunks of 128.
// smem: Qs[128][72] | Wks[128][72] | Wvs[16][1032] | bks[1024]  (~74 KB)
// ---------------------------------------------------------------------------
#define ATT_SMEM_BYTES (128 * 72 * 2 + 128 * 72 * 2 + 16 * 1032 * 2 + 1024 * 4)

__global__ __launch_bounds__(256)
void attn_flash(const __half* __restrict__ Q16, const __half* __restrict__ Wk16,
                const float* __restrict__ bk, const __half* __restrict__ Wv16,
                const float* __restrict__ bv, __half* __restrict__ V16)
{
    extern __shared__ char smraw[];
    __half* Qs  = (__half*)smraw;               // [128][72]
    __half* Wks = Qs + 128 * 72;                // [128][72]
    __half* Wvs = Wks + 128 * 72;               // [16][1032]
    float*  bks = (float*)(Wvs + 16 * 1032);    // [1024]

    const int tid = threadIdx.x;
    const int warp = tid >> 5, lane = tid & 31;
    const int qr = lane >> 2, grp = lane & 3;
    const int row0 = blockIdx.x * 128;

    // load Q tile (128 x 64 halves)
    #pragma unroll
    for (int i = 0; i < 4; i++) {
        int v = tid + 256 * i;
        *(float4*)&Qs[(v >> 3) * 72 + (v & 7) * 8] =
            *(const float4*)&Q16[(long)(row0 + (v >> 3)) * 64 + (v & 7) * 8];
    }
    // load Wv (16 x 1024 halves)
    #pragma unroll
    for (int i = 0; i < 8; i++) {
        int v = tid + 256 * i;
        int r = v >> 7, c = v & 127;
        *(float4*)&Wvs[r * 1032 + c * 8] = *(const float4*)&Wv16[r * 1024 + c * 8];
    }
    // load bk (1024 f32)
    ((float4*)bks)[tid] = ((const float4*)bk)[tid];
    __syncthreads();

    const float NEG_INF = -1e30f;
    float mA = NEG_INF, mB = NEG_INF, lA = 0.f, lB = 0.f;
    float o[2][4] = {};

    for (int ch = 0; ch < 8; ch++) {
        if (ch) __syncthreads();
        // load Wk chunk (rows ch*128 .. +127)
        #pragma unroll
        for (int i = 0; i < 4; i++) {
            int v = tid + 256 * i;
            *(float4*)&Wks[(v >> 3) * 72 + (v & 7) * 8] =
                *(const float4*)&Wk16[(long)(ch * 128 + (v >> 3)) * 64 + (v & 7) * 8];
        }
        __syncthreads();

        // ---- S = Qtile @ Wk_chunk^T : warp computes 16 rows x 128 cols ----
        float cc[16][4] = {};
        #pragma unroll
        for (int kk = 0; kk < 4; kk++) {
            int kb = kk * 16;
            uint32_t a[4];
            int r = warp * 16 + qr;
            a[0] = *(const uint32_t*)&Qs[r * 72 + kb + grp * 2];
            a[1] = *(const uint32_t*)&Qs[(r + 8) * 72 + kb + grp * 2];
            a[2] = *(const uint32_t*)&Qs[r * 72 + kb + 8 + grp * 2];
            a[3] = *(const uint32_t*)&Qs[(r + 8) * 72 + kb + 8 + grp * 2];
            #pragma unroll
            for (int j = 0; j < 16; j++) {
                int n = j * 8 + qr;
                uint32_t b0 = *(const uint32_t*)&Wks[n * 72 + kb + grp * 2];
                uint32_t b1 = *(const uint32_t*)&Wks[n * 72 + kb + 8 + grp * 2];
                mma_f16(cc[j], a, b0, b1);
            }
        }

        // ---- bias + scale + row stats ----
        float vmA = NEG_INF, vmB = NEG_INF;
        #pragma unroll
        for (int j = 0; j < 16; j++) {
            int m = ch * 128 + j * 8 + grp * 2;
            float b0 = bks[m & 1023], b1 = bks[(m + 1) & 1023];
            cc[j][0] = (cc[j][0] + b0) * 0.125f;
            cc[j][1] = (cc[j][1] + b1) * 0.125f;
            cc[j][2] = (cc[j][2] + b0) * 0.125f;
            cc[j][3] = (cc[j][3] + b1) * 0.125f;
            vmA = fmaxf(vmA, fmaxf(cc[j][0], cc[j][1]));
            vmB = fmaxf(vmB, fmaxf(cc[j][2], cc[j][3]));
        }
        vmA = fmaxf(vmA, __shfl_xor_sync(0xffffffffu, vmA, 1));
        vmA = fmaxf(vmA, __shfl_xor_sync(0xffffffffu, vmA, 2));
        vmB = fmaxf(vmB, __shfl_xor_sync(0xffffffffu, vmB, 1));
        vmB = fmaxf(vmB, __shfl_xor_sync(0xffffffffu, vmB, 2));

        float nmA = fmaxf(mA, vmA), nmB = fmaxf(mB, vmB);
        float fA = __expf(mA - nmA), fB = __expf(mB - nmB);
        mA = nmA; mB = nmB;
        #pragma unroll
        for (int t = 0; t < 2; t++) {
            o[t][0] *= fA; o[t][1] *= fA; o[t][2] *= fB; o[t][3] *= fB;
        }
        lA *= fA; lB *= fB;

        // ---- P = exp(S - m), pack to fp16 A-fragments, accumulate l ----
        float sA = 0.f, sB = 0.f;
        uint32_t pa[16], pb[16];
        #pragma unroll
        for (int j = 0; j < 16; j++) {
            float p0 = __expf(cc[j][0] - nmA), p1 = __expf(cc[j][1] - nmA);
            float p2 = __expf(cc[j][2] - nmB), p3 = __expf(cc[j][3] - nmB);
            sA += p0 + p1; sB += p2 + p3;
            __half2 hA = __floats2half2_rn(p0, p1);
            __half2 hB = __floats2half2_rn(p2, p3);
            pa[j] = *(uint32_t*)&hA;
            pb[j] = *(uint32_t*)&hB;
        }
        sA += __shfl_xor_sync(0xffffffffu, sA, 1);
        sA += __shfl_xor_sync(0xffffffffu, sA, 2);
        sB += __shfl_xor_sync(0xffffffffu, sB, 1);
        sB += __shfl_xor_sync(0xffffffffu, sB, 2);
        lA += sA; lB += sB;

        // ---- O += P @ Wv_chunk^T  (k = 128 chunk cols, n = 16 v) ----
        #pragma unroll
        for (int kk2 = 0; kk2 < 8; kk2++) {
            uint32_t a[4] = { pa[2 * kk2], pb[2 * kk2], pa[2 * kk2 + 1], pb[2 * kk2 + 1] };
            #pragma unroll
            for (int t = 0; t < 2; t++) {
                int n = t * 8 + qr;
                uint32_t b0 = *(const uint32_t*)&Wvs[n * 1032 + ch * 128 + kk2 * 16 + grp * 2];
                uint32_t b1 = *(const uint32_t*)&Wvs[n * 1032 + ch * 128 + kk2 * 16 + 8 + grp * 2];
                mma_f16(o[t], a, b0, b1);
            }
        }
    }

    // ---- epilogue: normalize, +bv, write V16 (fp16) ----
    float iA = 1.f / lA, iB = 1.f / lB;
    int rowA = row0 + warp * 16 + qr;
    #pragma unroll
    for (int t = 0; t < 2; t++) {
        int v0 = t * 8 + grp * 2;
        float b0 = bv[v0], b1 = bv[v0 + 1];
        *(__half2*)&V16[(long)rowA * 16 + v0] =
            __floats2half2_rn(o[t][0] * iA + b0, o[t][1] * iA + b1);
        *(__half2*)&V16[(long)(rowA + 8) * 16 + v0] =
            __floats2half2_rn(o[t][2] * iB + b0, o[t][3] * iB + b1);
    }
}

// ---------------------------------------------------------------------------
extern "C" void kernel_launch(void* const* d_in, const int* in_sizes, int n_in,
                              void* d_out, int out_size)
{
    const float* x  = (const float*)d_in[0];
    const float* Wq = (const float*)d_in[1];
    const float* bq = (const float*)d_in[2];
    const float* Wk = (const float*)d_in[3];
    const float* bk = (const float*)d_in[4];
    const float* Wv = (const float*)d_in[5];
    const float* bv = (const float*)d_in[6];
    const float* Wh = (const float*)d_in[7];
    const float* bh = (const float*)d_in[8];
    float* out = (float*)d_out;

    __half *x16, *Wq16, *Wk16, *Wv16, *Wh16, *Q16, *V16;
    cudaGetSymbolAddress((void**)&x16,  g_x16);
    cudaGetSymbolAddress((void**)&Wq16, g_Wq16);
    cudaGetSymbolAddress((void**)&Wk16, g_Wk16);
    cudaGetSymbolAddress((void**)&Wv16, g_Wv16);
    cudaGetSymbolAddress((void**)&Wh16, g_Wh16);
    cudaGetSymbolAddress((void**)&Q16,  g_Q16);
    cudaGetSymbolAddress((void**)&V16,  g_V16);

    cudaFuncSetAttribute(attn_flash, cudaFuncAttributeMaxDynamicSharedMemorySize,
                         ATT_SMEM_BYTES);

    // fp32 -> fp16 conversions
    cvt_f2h<<<(524288 + 255) / 256, 256>>>((const float4*)x,  (__half2*)x16,  524288);
    cvt_f2h<<<(262144 + 255) / 256, 256>>>((const float4*)Wq, (__half2*)Wq16, 262144);
    cvt_f2h<<<(16384  + 255) / 256, 256>>>((const float4*)Wk, (__half2*)Wk16, 16384);
    cvt_f2h<<<(4096   + 255) / 256, 256>>>((const float4*)Wv, (__half2*)Wv16, 4096);
    cvt_f2h<<<(262144 + 255) / 256, 256>>>((const float4*)Wh, (__half2*)Wh16, 262144);

    // Stage 1: Q16 = x16 @ Wq16^T + bq   (2048 x 1024 x 1024, fp16 out)
    hgemm_nt<true><<<dim3(8, 16, 1), 256>>>(x16, 0, 1024, Wq16, bq,
                                            Q16, 0, 1024, 2048, 1024, 1024);

    // Stage 2: flash attention over all 32768 (pos,head) rows -> V16 (32768 x 16)
    attn_flash<<<256, 256, ATT_SMEM_BYTES>>>(Q16, Wk16, bk, Wv16, bv, V16);

    // Stage 3: out[b,w,:] = V16[b, w*256 : +1024] @ Wh16^T + bh  (lda=256 overlap)
    hgemm_nt<false><<<dim3(8, 8, 2), 256>>>(V16, 262144, 256, Wh16, bh,
                                            out, 1021L * 1024, 1024, 1021, 1024, 1024);
}

// round 4
// speedup vs baseline: 6.9730x; 1.2276x over previous
#include <cuda_runtime.h>
#include <cuda_fp16.h>
#include <cstdint>

// D=1024, H=16, M=1024, K=4, ST=1, HD=64, VD=16
// Pipeline (all tensor-core fp16 mma, fp32 accum):
//   Q = x @ Wq^T + bq                         (2048 x 1024 x 1024)
//   Qh = reshape(Q) -> (32768 x 64) rows = (pos,head)
//   flash: S = Qh @ Wk^T (+bk)/8 ; att=softmax ; V = att @ Wv^T + bv  (32768x16)
//   out[b,w,:] = V[b, w*256 : w*256+1024] @ Wh^T + bh   (overlap => lda=256)

__device__ __half g_x16 [2048 * 1024];
__device__ __half g_Wq16[1024 * 1024];
__device__ __half g_Wk16[1024 * 64];
__device__ __half g_Wv16[16 * 1024];
__device__ __half g_Wh16[1024 * 1024];
__device__ __half g_Q16 [2048 * 1024];
__device__ __half g_V16 [2048 * 256 + 2048];   // +pad: stage-3 tail rows overrun

// ---------------------------------------------------------------------------
__device__ __forceinline__ void cp_async16(void* smem, const void* gmem)
{
    uint32_t s = (uint32_t)__cvta_generic_to_shared(smem);
    asm volatile("cp.async.cg.shared.global [%0], [%1], 16;\n" :: "r"(s), "l"(gmem));
}
__device__ __forceinline__ void cp_commit()
{
    asm volatile("cp.async.commit_group;\n");
}
template <int N>
__device__ __forceinline__ void cp_wait()
{
    asm volatile("cp.async.wait_group %0;\n" :: "n"(N));
}

// ---------------------------------------------------------------------------
// Fused fp32 -> fp16 conversion for all 5 tensors in ONE launch.
// Segments (float4 counts): x 524288 | Wq 262144 | Wk 16384 | Wv 4096 | Wh 262144
// ---------------------------------------------------------------------------
__global__ __launch_bounds__(256)
void cvt_all(const float4* __restrict__ x,  const float4* __restrict__ wq,
             const float4* __restrict__ wk, const float4* __restrict__ wv,
             const float4* __restrict__ wh,
             __half2* ox, __half2* owq, __half2* owk, __half2* owv, __half2* owh)
{
    int i = blockIdx.x * blockDim.x + threadIdx.x;
    const float4* in;
    __half2* out;
    int off;
    if      (i <  524288) { in = x;  out = ox;  off = i; }
    else if (i <  786432) { in = wq; out = owq; off = i - 524288; }
    else if (i <  802816) { in = wk; out = owk; off = i - 786432; }
    else if (i <  806912) { in = wv; out = owv; off = i - 802816; }
    else if (i < 1069056) { in = wh; out = owh; off = i - 806912; }
    else return;
    float4 v = in[off];
    out[2 * off]     = __floats2half2_rn(v.x, v.y);
    out[2 * off + 1] = __floats2half2_rn(v.z, v.w);
}

// ---------------------------------------------------------------------------
__device__ __forceinline__ void mma_f16(float* c, const uint32_t* a, uint32_t b0, uint32_t b1)
{
    asm volatile(
        "mma.sync.aligned.m16n8k16.row.col.f32.f16.f16.f32 "
        "{%0,%1,%2,%3}, {%4,%5,%6,%7}, {%8,%9}, {%0,%1,%2,%3};\n"
        : "+f"(c[0]), "+f"(c[1]), "+f"(c[2]), "+f"(c[3])
        : "r"(a[0]), "r"(a[1]), "r"(a[2]), "r"(a[3]), "r"(b0), "r"(b1));
}

// ---------------------------------------------------------------------------
// HGEMM NT, cp.async 2-stage pipelined: C[r][c] = sum_k A[r][k]*B[c][k] + bias[c]
// BM=BN=128, BK=32, 256 threads (8 warps, warp tile 32x64).
// smem stride 40 halves (80B rows, 16B aligned) -> conflict-free fragments.
// ---------------------------------------------------------------------------
template <bool HALF_OUT>
__global__ __launch_bounds__(256)
void hgemm_nt(const __half* __restrict__ A, long aBatch, int lda,
              const __half* __restrict__ B,
              const float* __restrict__ bias,
              void* __restrict__ Cv, long cBatch, int ldc,
              int M, int N, int K)
{
    __shared__ __half As[2][128][40];
    __shared__ __half Bs[2][128][40];

    const int tid = threadIdx.x;
    const int warp = tid >> 5, lane = tid & 31;
    const int qr = lane >> 2, grp = lane & 3;
    const int wr = (warp & 3) * 32;         // warp row in tile
    const int wc = (warp >> 2) * 64;        // warp col in tile
    const int row0 = blockIdx.y * 128;
    const int col0 = blockIdx.x * 128;

    const __half* Ab = A + (long)blockIdx.z * aBatch;

    // per-thread load coords: 2 float4 per matrix per stage
    const int lr0 = tid >> 2, lc0 = (tid & 3) * 8;
    const int lr1 = (tid + 256) >> 2, lc1 = ((tid + 256) & 3) * 8;

    float acc[16][4] = {};                  // [mi*8+nj][4]

    const int nIter = K >> 5;

    // prologue: stage 0
    cp_async16(&As[0][lr0][lc0], &Ab[(long)(row0 + lr0) * lda + lc0]);
    cp_async16(&As[0][lr1][lc1], &Ab[(long)(row0 + lr1) * lda + lc1]);
    cp_async16(&Bs[0][lr0][lc0], &B[(long)(col0 + lr0) * 1024 + lc0]);
    cp_async16(&Bs[0][lr1][lc1], &B[(long)(col0 + lr1) * 1024 + lc1]);
    cp_commit();

    for (int it = 0; it < nIter; it++) {
        if (it + 1 < nIter) {
            int k0 = (it + 1) << 5;
            int nb = (it + 1) & 1;
            cp_async16(&As[nb][lr0][lc0], &Ab[(long)(row0 + lr0) * lda + k0 + lc0]);
            cp_async16(&As[nb][lr1][lc1], &Ab[(long)(row0 + lr1) * lda + k0 + lc1]);
            cp_async16(&Bs[nb][lr0][lc0], &B[(long)(col0 + lr0) * 1024 + k0 + lc0]);
            cp_async16(&Bs[nb][lr1][lc1], &B[(long)(col0 + lr1) * 1024 + k0 + lc1]);
            cp_commit();
            cp_wait<1>();
        } else {
            cp_wait<0>();
        }
        __syncthreads();

        const int cb = it & 1;
        #pragma unroll
        for (int kk = 0; kk < 32; kk += 16) {
            uint32_t af[2][4];
            #pragma unroll
            for (int mi = 0; mi < 2; mi++) {
                int r = wr + mi * 16 + qr;
                af[mi][0] = *(const uint32_t*)&As[cb][r][kk + grp * 2];
                af[mi][1] = *(const uint32_t*)&As[cb][r + 8][kk + grp * 2];
                af[mi][2] = *(const uint32_t*)&As[cb][r][kk + 8 + grp * 2];
                af[mi][3] = *(const uint32_t*)&As[cb][r + 8][kk + 8 + grp * 2];
            }
            #pragma unroll
            for (int nj = 0; nj < 8; nj++) {
                int n = wc + nj * 8 + qr;
                uint32_t b0 = *(const uint32_t*)&Bs[cb][n][kk + grp * 2];
                uint32_t b1 = *(const uint32_t*)&Bs[cb][n][kk + 8 + grp * 2];
                mma_f16(acc[0 * 8 + nj], af[0], b0, b1);
                mma_f16(acc[1 * 8 + nj], af[1], b0, b1);
            }
        }
        __syncthreads();
    }

    // epilogue
    #pragma unroll
    for (int mi = 0; mi < 2; mi++) {
        #pragma unroll
        for (int nj = 0; nj < 8; nj++) {
            float* c = acc[mi * 8 + nj];
            int col = col0 + wc + nj * 8 + grp * 2;
            float b0 = bias[col], b1 = bias[col + 1];
            int rA = row0 + wr + mi * 16 + qr;
            int rB = rA + 8;
            if (HALF_OUT) {
                __half* C = (__half*)Cv + (long)blockIdx.z * cBatch;
                if (rA < M) *(__half2*)&C[(long)rA * ldc + col] = __floats2half2_rn(c[0] + b0, c[1] + b1);
                if (rB < M) *(__half2*)&C[(long)rB * ldc + col] = __floats2half2_rn(c[2] + b0, c[3] + b1);
            } else {
                float* C = (float*)Cv + (long)blockIdx.z * cBatch;
                if (rA < M) *(float2*)&C[(long)rA * ldc + col] = make_float2(c[0] + b0, c[1] + b1);
                if (rB < M) *(float2*)&C[(long)rB * ldc + col] = make_float2(c[2] + b0, c[3] + b1);
            }
        }
    }
}

// ---------------------------------------------------------------------------
// Flash attention: rows = Qh (32768 x 64), K = Wk (1024 x 64), V = Wv^T (1024 x 16)
// 128 rows/CTA (256 CTAs), 8 warps x 16 rows, online softmax over 8 m-chunks of 128.
// Wk chunks double-buffered via cp.async.
// smem: Qs[128][72] | Wks[2][128][72] | Wvs[16][1032] | bks[1024]  (~92 KB, 2 CTA/SM)
// ---------------------------------------------------------------------------
#define ATT_SMEM_BYTES (128 * 72 * 2 + 2 * 128 * 72 * 2 + 16 * 1032 * 2 + 1024 * 4)

__global__ __launch_bounds__(256)
void attn_flash(const __half* __restrict__ Q16, const __half* __restrict__ Wk16,
                const float* __restrict__ bk, const __half* __restrict__ Wv16,
                const float* __restrict__ bv, __half* __restrict__ V16)
{
    extern __shared__ char smraw[];
    __half* Qs  = (__half*)smraw;               // [128][72]
    __half* Wks = Qs + 128 * 72;                // [2][128][72]
    __half* Wvs = Wks + 2 * 128 * 72;           // [16][1032]
    float*  bks = (float*)(Wvs + 16 * 1032);    // [1024]

    const int tid = threadIdx.x;
    const int warp = tid >> 5, lane = tid & 31;
    const int qr = lane >> 2, grp = lane & 3;
    const int row0 = blockIdx.x * 128;

    // prologue: issue Wk chunk 0 via cp.async first (deepest latency), then others
    #pragma unroll
    for (int i = 0; i < 4; i++) {
        int v = tid + 256 * i;
        cp_async16(&Wks[(v >> 3) * 72 + (v & 7) * 8],
                   &Wk16[(long)(v >> 3) * 64 + (v & 7) * 8]);
    }
    cp_commit();

    // load Q tile (128 x 64 halves)
    #pragma unroll
    for (int i = 0; i < 4; i++) {
        int v = tid + 256 * i;
        *(float4*)&Qs[(v >> 3) * 72 + (v & 7) * 8] =
            *(const float4*)&Q16[(long)(row0 + (v >> 3)) * 64 + (v & 7) * 8];
    }
    // load Wv (16 x 1024 halves)
    #pragma unroll
    for (int i = 0; i < 8; i++) {
        int v = tid + 256 * i;
        int r = v >> 7, c = v & 127;
        *(float4*)&Wvs[r * 1032 + c * 8] = *(const float4*)&Wv16[r * 1024 + c * 8];
    }
    // load bk (1024 f32)
    ((float4*)bks)[tid] = ((const float4*)bk)[tid];

    const float NEG_INF = -1e30f;
    float mA = NEG_INF, mB = NEG_INF, lA = 0.f, lB = 0.f;
    float o[2][4] = {};

    for (int ch = 0; ch < 8; ch++) {
        if (ch < 7) {
            // prefetch chunk ch+1 into alternate buffer
            __half* Wkn = Wks + ((ch + 1) & 1) * 128 * 72;
            #pragma unroll
            for (int i = 0; i < 4; i++) {
                int v = tid + 256 * i;
                cp_async16(&Wkn[(v >> 3) * 72 + (v & 7) * 8],
                           &Wk16[(long)((ch + 1) * 128 + (v >> 3)) * 64 + (v & 7) * 8]);
            }
            cp_commit();
            cp_wait<1>();
        } else {
            cp_wait<0>();
        }
        __syncthreads();

        const __half* Wkc = Wks + (ch & 1) * 128 * 72;

        // ---- S = Qtile @ Wk_chunk^T : warp computes 16 rows x 128 cols ----
        float cc[16][4] = {};
        #pragma unroll
        for (int kk = 0; kk < 4; kk++) {
            int kb = kk * 16;
            uint32_t a[4];
            int r = warp * 16 + qr;
            a[0] = *(const uint32_t*)&Qs[r * 72 + kb + grp * 2];
            a[1] = *(const uint32_t*)&Qs[(r + 8) * 72 + kb + grp * 2];
            a[2] = *(const uint32_t*)&Qs[r * 72 + kb + 8 + grp * 2];
            a[3] = *(const uint32_t*)&Qs[(r + 8) * 72 + kb + 8 + grp * 2];
            #pragma unroll
            for (int j = 0; j < 16; j++) {
                int n = j * 8 + qr;
                uint32_t b0 = *(const uint32_t*)&Wkc[n * 72 + kb + grp * 2];
                uint32_t b1 = *(const uint32_t*)&Wkc[n * 72 + kb + 8 + grp * 2];
                mma_f16(cc[j], a, b0, b1);
            }
        }

        // ---- bias + scale + row stats ----
        float vmA = NEG_INF, vmB = NEG_INF;
        #pragma unroll
        for (int j = 0; j < 16; j++) {
            int m = ch * 128 + j * 8 + grp * 2;
            float b0 = bks[m & 1023], b1 = bks[(m + 1) & 1023];
            cc[j][0] = (cc[j][0] + b0) * 0.125f;
            cc[j][1] = (cc[j][1] + b1) * 0.125f;
            cc[j][2] = (cc[j][2] + b0) * 0.125f;
            cc[j][3] = (cc[j][3] + b1) * 0.125f;
            vmA = fmaxf(vmA, fmaxf(cc[j][0], cc[j][1]));
            vmB = fmaxf(vmB, fmaxf(cc[j][2], cc[j][3]));
        }
        vmA = fmaxf(vmA, __shfl_xor_sync(0xffffffffu, vmA, 1));
        vmA = fmaxf(vmA, __shfl_xor_sync(0xffffffffu, vmA, 2));
        vmB = fmaxf(vmB, __shfl_xor_sync(0xffffffffu, vmB, 1));
        vmB = fmaxf(vmB, __shfl_xor_sync(0xffffffffu, vmB, 2));

        float nmA = fmaxf(mA, vmA), nmB = fmaxf(mB, vmB);
        float fA = __expf(mA - nmA), fB = __expf(mB - nmB);
        mA = nmA; mB = nmB;
        #pragma unroll
        for (int t = 0; t < 2; t++) {
            o[t][0] *= fA; o[t][1] *= fA; o[t][2] *= fB; o[t][3] *= fB;
        }
        lA *= fA; lB *= fB;

        // ---- P = exp(S - m), pack to fp16 A-fragments, accumulate l ----
        float sA = 0.f, sB = 0.f;
        uint32_t pa[16], pb[16];
        #pragma unroll
        for (int j = 0; j < 16; j++) {
            float p0 = __expf(cc[j][0] - nmA), p1 = __expf(cc[j][1] - nmA);
            float p2 = __expf(cc[j][2] - nmB), p3 = __expf(cc[j][3] - nmB);
            sA += p0 + p1; sB += p2 + p3;
            __half2 hA = __floats2half2_rn(p0, p1);
            __half2 hB = __floats2half2_rn(p2, p3);
            pa[j] = *(uint32_t*)&hA;
            pb[j] = *(uint32_t*)&hB;
        }
        sA += __shfl_xor_sync(0xffffffffu, sA, 1);
        sA += __shfl_xor_sync(0xffffffffu, sA, 2);
        sB += __shfl_xor_sync(0xffffffffu, sB, 1);
        sB += __shfl_xor_sync(0xffffffffu, sB, 2);
        lA += sA; lB += sB;

        // ---- O += P @ Wv_chunk^T  (k = 128 chunk cols, n = 16 v) ----
        #pragma unroll
        for (int kk2 = 0; kk2 < 8; kk2++) {
            uint32_t a[4] = { pa[2 * kk2], pb[2 * kk2], pa[2 * kk2 + 1], pb[2 * kk2 + 1] };
            #pragma unroll
            for (int t = 0; t < 2; t++) {
                int n = t * 8 + qr;
                uint32_t b0 = *(const uint32_t*)&Wvs[n * 1032 + ch * 128 + kk2 * 16 + grp * 2];
                uint32_t b1 = *(const uint32_t*)&Wvs[n * 1032 + ch * 128 + kk2 * 16 + 8 + grp * 2];
                mma_f16(o[t], a, b0, b1);
            }
        }
        __syncthreads();   // protect Wks[ch&1] before next prefetch overwrites it
    }

    // ---- epilogue: normalize, +bv, write V16 (fp16) ----
    float iA = 1.f / lA, iB = 1.f / lB;
    int rowA = row0 + warp * 16 + qr;
    #pragma unroll
    for (int t = 0; t < 2; t++) {
        int v0 = t * 8 + grp * 2;
        float b0 = bv[v0], b1 = bv[v0 + 1];
        *(__half2*)&V16[(long)rowA * 16 + v0] =
            __floats2half2_rn(o[t][0] * iA + b0, o[t][1] * iA + b1);
        *(__half2*)&V16[(long)(rowA + 8) * 16 + v0] =
            __floats2half2_rn(o[t][2] * iB + b0, o[t][3] * iB + b1);
    }
}

// ---------------------------------------------------------------------------
extern "C" void kernel_launch(void* const* d_in, const int* in_sizes, int n_in,
                              void* d_out, int out_size)
{
    const float* x  = (const float*)d_in[0];
    const float* Wq = (const float*)d_in[1];
    const float* bq = (const float*)d_in[2];
    const float* Wk = (const float*)d_in[3];
    const float* bk = (const float*)d_in[4];
    const float* Wv = (const float*)d_in[5];
    const float* bv = (const float*)d_in[6];
    const float* Wh = (const float*)d_in[7];
    const float* bh = (const float*)d_in[8];
    float* out = (float*)d_out;

    __half *x16, *Wq16, *Wk16, *Wv16, *Wh16, *Q16, *V16;
    cudaGetSymbolAddress((void**)&x16,  g_x16);
    cudaGetSymbolAddress((void**)&Wq16, g_Wq16);
    cudaGetSymbolAddress((void**)&Wk16, g_Wk16);
    cudaGetSymbolAddress((void**)&Wv16, g_Wv16);
    cudaGetSymbolAddress((void**)&Wh16, g_Wh16);
    cudaGetSymbolAddress((void**)&Q16,  g_Q16);
    cudaGetSymbolAddress((void**)&V16,  g_V16);

    cudaFuncSetAttribute(attn_flash, cudaFuncAttributeMaxDynamicSharedMemorySize,
                         ATT_SMEM_BYTES);

    // fp32 -> fp16 conversion (single fused launch)
    cvt_all<<<(1069056 + 255) / 256, 256>>>(
        (const float4*)x, (const float4*)Wq, (const float4*)Wk,
        (const float4*)Wv, (const float4*)Wh,
        (__half2*)x16, (__half2*)Wq16, (__half2*)Wk16,
        (__half2*)Wv16, (__half2*)Wh16);

    // Stage 1: Q16 = x16 @ Wq16^T + bq   (2048 x 1024 x 1024, fp16 out)
    hgemm_nt<true><<<dim3(8, 16, 1), 256>>>(x16, 0, 1024, Wq16, bq,
                                            Q16, 0, 1024, 2048, 1024, 1024);

    // Stage 2: flash attention over all 32768 (pos,head) rows -> V16 (32768 x 16)
    attn_flash<<<256, 256, ATT_SMEM_BYTES>>>(Q16, Wk16, bk, Wv16, bv, V16);

    // Stage 3: out[b,w,:] = V16[b, w*256 : +1024] @ Wh16^T + bh  (lda=256 overlap)
    hgemm_nt<false><<<dim3(8, 8, 2), 256>>>(V16, 262144, 256, Wh16, bh,
                                            out, 1021L * 1024, 1024, 1021, 1024, 1024);
}

// round 6
// speedup vs baseline: 7.6673x; 1.0996x over previous
#include <cuda_runtime.h>
#include <cuda_fp16.h>
#include <cstdint>

// D=1024, H=16, M=1024, K=4, ST=1, HD=64, VD=16
// Pipeline (all tensor-core fp16 mma.sync, fp32 accum):
//   Q = x @ Wq^T + bq                         (2048 x 1024 x 1024)
//   flash: S = Qh @ Wk^T (+bk)/8 ; att=softmax ; V = att @ Wv^T + bv  (32768x16)
//   out[b,w,:] = V[b, w*256 : +1024] @ Wh^T + bh   (overlap => lda=256)

__device__ __half g_x16 [2048 * 1024];
__device__ __half g_Wq16[1024 * 1024];
__device__ __half g_Wk16[1024 * 64];
__device__ __half g_Wv16[16 * 1024];
__device__ __half g_Wh16[1024 * 1024];
__device__ __half g_Q16 [2048 * 1024];
__device__ __half g_V16 [2048 * 256 + 2048];   // +pad: stage-3 tail rows overrun

// ---------------------------------------------------------------------------
__device__ __forceinline__ void cp_async16(void* smem, const void* gmem)
{
    uint32_t s = (uint32_t)__cvta_generic_to_shared(smem);
    asm volatile("cp.async.cg.shared.global [%0], [%1], 16;\n" :: "r"(s), "l"(gmem));
}
__device__ __forceinline__ void cp_commit()
{
    asm volatile("cp.async.commit_group;\n");
}
template <int N>
__device__ __forceinline__ void cp_wait()
{
    asm volatile("cp.async.wait_group %0;\n" :: "n"(N));
}

__device__ __forceinline__ void ldsm_x4(uint32_t& r0, uint32_t& r1, uint32_t& r2,
                                        uint32_t& r3, uint32_t addr)
{
    asm volatile("ldmatrix.sync.aligned.m8n8.x4.shared.b16 {%0,%1,%2,%3}, [%4];"
                 : "=r"(r0), "=r"(r1), "=r"(r2), "=r"(r3) : "r"(addr));
}

__device__ __forceinline__ void mma_f16(float* c, const uint32_t* a, uint32_t b0, uint32_t b1)
{
    asm volatile(
        "mma.sync.aligned.m16n8k16.row.col.f32.f16.f16.f32 "
        "{%0,%1,%2,%3}, {%4,%5,%6,%7}, {%8,%9}, {%0,%1,%2,%3};\n"
        : "+f"(c[0]), "+f"(c[1]), "+f"(c[2]), "+f"(c[3])
        : "r"(a[0]), "r"(a[1]), "r"(a[2]), "r"(a[3]), "r"(b0), "r"(b1));
}

// ---------------------------------------------------------------------------
// Fused fp32 -> fp16 conversion for all 5 tensors in ONE launch.
// ---------------------------------------------------------------------------
__global__ __launch_bounds__(256)
void cvt_all(const float4* __restrict__ x,  const float4* __restrict__ wq,
             const float4* __restrict__ wk, const float4* __restrict__ wv,
             const float4* __restrict__ wh,
             __half2* ox, __half2* owq, __half2* owk, __half2* owv, __half2* owh)
{
    int i = blockIdx.x * blockDim.x + threadIdx.x;
    const float4* in;
    __half2* out;
    int off;
    if      (i <  524288) { in = x;  out = ox;  off = i; }
    else if (i <  786432) { in = wq; out = owq; off = i - 524288; }
    else if (i <  802816) { in = wk; out = owk; off = i - 786432; }
    else if (i <  806912) { in = wv; out = owv; off = i - 802816; }
    else if (i < 1069056) { in = wh; out = owh; off = i - 806912; }
    else return;
    float4 v = in[off];
    out[2 * off]     = __floats2half2_rn(v.x, v.y);
    out[2 * off + 1] = __floats2half2_rn(v.z, v.w);
}

// ---------------------------------------------------------------------------
// HGEMM NT: C[r][c] = sum_k A[r][k]*B[c][k] + bias[c]
// BM=BN=128, BK=64, K=1024 (16 chunks). 256 threads, 8 warps (warp tile 32x64).
// 3-stage cp.async ring, ONE __syncthreads per chunk, ldmatrix fragment loads.
// smem: per stage A[128][72] + B[128][72] halves = 36864 B; 3 stages = 110592 B.
// ---------------------------------------------------------------------------
#define G_STAGE 36864
#define G_SMEM  (3 * G_STAGE)

template <bool HALF_OUT>
__global__ __launch_bounds__(256)
void hgemm_nt(const __half* __restrict__ A, long aBatch, int lda,
              const __half* __restrict__ B,
              const float* __restrict__ bias,
              void* __restrict__ Cv, long cBatch, int ldc, int M)
{
    extern __shared__ char sm[];
    const uint32_t smem_u = (uint32_t)__cvta_generic_to_shared(sm);

    const int tid = threadIdx.x;
    const int warp = tid >> 5, lane = tid & 31;
    const int qr = lane >> 2, grp = lane & 3;
    const int wr = (warp & 3) * 32;         // warp row in tile
    const int wc = (warp >> 2) * 64;        // warp col in tile
    const int row0 = blockIdx.y * 128;
    const int col0 = blockIdx.x * 128;

    const __half* Ab = A + (long)blockIdx.z * aBatch;
    const __half* Bb = B + (long)col0 * 1024;

    // per-thread cp.async slots: 4 x 16B per matrix per chunk (128 rows x 64 halves)
    uint32_t soff[4];
    long aoff[4], boff[4];
    #pragma unroll
    for (int i = 0; i < 4; i++) {
        int u = tid + 256 * i;
        int r = u >> 3;              // 0..127
        int c8 = (u & 7) * 8;        // half col
        soff[i] = r * 144 + c8 * 2;  // byte offset, stride 72 halves
        aoff[i] = (long)(row0 + r) * lda + c8;
        boff[i] = (long)r * 1024 + c8;
    }

    auto load_chunk = [&](int ch) {
        char* base = sm + (ch % 3) * G_STAGE;
        const int k0 = ch * 64;
        #pragma unroll
        for (int i = 0; i < 4; i++) {
            cp_async16(base + soff[i],         Ab + aoff[i] + k0);
            cp_async16(base + 18432 + soff[i], Bb + boff[i] + k0);
        }
        cp_commit();
    };

    // ldmatrix lane base offsets (bytes within stage)
    const uint32_t aLane = (uint32_t)((wr + (lane & 7) + ((lane >> 3) & 1) * 8) * 144
                                      + (lane >> 4) * 16);
    const uint32_t bLane = (uint32_t)(18432 + (wc + (lane & 7) + (lane >> 4) * 8) * 144
                                      + ((lane >> 3) & 1) * 16);

    float acc[2][8][4] = {};

    load_chunk(0);
    load_chunk(1);

    for (int ch = 0; ch < 16; ch++) {
        if (ch < 15) cp_wait<1>(); else cp_wait<0>();
        __syncthreads();
        if (ch + 2 < 16) load_chunk(ch + 2);

        const uint32_t sb = smem_u + (ch % 3) * G_STAGE;
        const uint32_t aAdr = sb + aLane;
        const uint32_t bAdr = sb + bLane;

        #pragma unroll
        for (int kk = 0; kk < 4; kk++) {
            uint32_t a0[4], a1[4];
            ldsm_x4(a0[0], a0[1], a0[2], a0[3], aAdr + kk * 32);
            ldsm_x4(a1[0], a1[1], a1[2], a1[3], aAdr + kk * 32 + 16 * 144);
            #pragma unroll
            for (int pj = 0; pj < 4; pj++) {
                uint32_t q[4];
                ldsm_x4(q[0], q[1], q[2], q[3], bAdr + kk * 32 + pj * 16 * 144);
                mma_f16(acc[0][2 * pj],     a0, q[0], q[1]);
                mma_f16(acc[0][2 * pj + 1], a0, q[2], q[3]);
                mma_f16(acc[1][2 * pj],     a1, q[0], q[1]);
                mma_f16(acc[1][2 * pj + 1], a1, q[2], q[3]);
            }
        }
    }

    // epilogue
    #pragma unroll
    for (int mi = 0; mi < 2; mi++) {
        #pragma unroll
        for (int nj = 0; nj < 8; nj++) {
            float* c = acc[mi][nj];
            int col = col0 + wc + nj * 8 + grp * 2;
            float b0 = bias[col], b1 = bias[col + 1];
            int rA = row0 + wr + mi * 16 + qr;
            int rB = rA + 8;
            if (HALF_OUT) {
                __half* C = (__half*)Cv + (long)blockIdx.z * cBatch;
                if (rA < M) *(__half2*)&C[(long)rA * ldc + col] = __floats2half2_rn(c[0] + b0, c[1] + b1);
                if (rB < M) *(__half2*)&C[(long)rB * ldc + col] = __floats2half2_rn(c[2] + b0, c[3] + b1);
            } else {
                float* C = (float*)Cv + (long)blockIdx.z * cBatch;
                if (rA < M) *(float2*)&C[(long)rA * ldc + col] = make_float2(c[0] + b0, c[1] + b1);
                if (rB < M) *(float2*)&C[(long)rB * ldc + col] = make_float2(c[2] + b0, c[3] + b1);
            }
        }
    }
}

// ---------------------------------------------------------------------------
// Flash attention: rows = Qh (32768 x 64), K = Wk (1024 x 64), V = Wv^T (1024 x 16)
// 128 rows/CTA (256 CTAs), 8 warps x 16 rows, online softmax over 8 m-chunks of 128.
// S-mma fragments via ldmatrix. Wk double-buffered via cp.async.
// smem: Qs[128][72] | Wks[2][128][72] | Wvs[16][1032] | bks[1024]  (~92 KB, 2 CTA/SM)
// ---------------------------------------------------------------------------
#define ATT_SMEM_BYTES (128 * 72 * 2 + 2 * 128 * 72 * 2 + 16 * 1032 * 2 + 1024 * 4)

__global__ __launch_bounds__(256)
void attn_flash(const __half* __restrict__ Q16, const __half* __restrict__ Wk16,
                const float* __restrict__ bk, const __half* __restrict__ Wv16,
                const float* __restrict__ bv, __half* __restrict__ V16)
{
    extern __shared__ char smraw[];
    __half* Qs  = (__half*)smraw;               // [128][72]
    __half* Wks = Qs + 128 * 72;                // [2][128][72]
    __half* Wvs = Wks + 2 * 128 * 72;           // [16][1032]
    float*  bks = (float*)(Wvs + 16 * 1032);    // [1024]

    const uint32_t smem_u = (uint32_t)__cvta_generic_to_shared(smraw);
    const int tid = threadIdx.x;
    const int warp = tid >> 5, lane = tid & 31;
    const int qr = lane >> 2, grp = lane & 3;
    const int row0 = blockIdx.x * 128;

    #pragma unroll
    for (int i = 0; i < 4; i++) {
        int v = tid + 256 * i;
        cp_async16(&Wks[(v >> 3) * 72 + (v & 7) * 8],
                   &Wk16[(long)(v >> 3) * 64 + (v & 7) * 8]);
    }
    cp_commit();

    #pragma unroll
    for (int i = 0; i < 4; i++) {
        int v = tid + 256 * i;
        *(float4*)&Qs[(v >> 3) * 72 + (v & 7) * 8] =
            *(const float4*)&Q16[(long)(row0 + (v >> 3)) * 64 + (v & 7) * 8];
    }
    #pragma unroll
    for (int i = 0; i < 8; i++) {
        int v = tid + 256 * i;
        int r = v >> 7, c = v & 127;
        *(float4*)&Wvs[r * 1032 + c * 8] = *(const float4*)&Wv16[r * 1024 + c * 8];
    }
    ((float4*)bks)[tid] = ((const float4*)bk)[tid];

    // ldmatrix lane addresses
    const uint32_t qAdr = smem_u
        + (uint32_t)((warp * 16 + (lane & 7) + ((lane >> 3) & 1) * 8) * 144
                     + (lane >> 4) * 16);
    const uint32_t wkLane = (uint32_t)(128 * 144
        + ((lane & 7) + (lane >> 4) * 8) * 144 + ((lane >> 3) & 1) * 16);

    const float NEG_INF = -1e30f;
    float mA = NEG_INF, mB = NEG_INF, lA = 0.f, lB = 0.f;
    float o[2][4] = {};

    for (int ch = 0; ch < 8; ch++) {
        if (ch < 7) {
            __half* Wkn = Wks + ((ch + 1) & 1) * 128 * 72;
            #pragma unroll
            for (int i = 0; i < 4; i++) {
                int v = tid + 256 * i;
                cp_async16(&Wkn[(v >> 3) * 72 + (v & 7) * 8],
                           &Wk16[(long)((ch + 1) * 128 + (v >> 3)) * 64 + (v & 7) * 8]);
            }
            cp_commit();
            cp_wait<1>();
        } else {
            cp_wait<0>();
        }
        __syncthreads();

        const uint32_t wkAdr = smem_u + wkLane + (uint32_t)((ch & 1) * 128 * 144);

        // ---- S = Qtile @ Wk_chunk^T via ldmatrix ----
        float cc[16][4] = {};
        #pragma unroll
        for (int kk = 0; kk < 4; kk++) {
            uint32_t a[4];
            ldsm_x4(a[0], a[1], a[2], a[3], qAdr + kk * 32);
            #pragma unroll
            for (int pj = 0; pj < 8; pj++) {
                uint32_t q[4];
                ldsm_x4(q[0], q[1], q[2], q[3], wkAdr + kk * 32 + pj * 16 * 144);
                mma_f16(cc[2 * pj],     a, q[0], q[1]);
                mma_f16(cc[2 * pj + 1], a, q[2], q[3]);
            }
        }

        // ---- bias + scale + row stats ----
        float vmA = NEG_INF, vmB = NEG_INF;
        #pragma unroll
        for (int j = 0; j < 16; j++) {
            int m = ch * 128 + j * 8 + grp * 2;
            float b0 = bks[m & 1023], b1 = bks[(m + 1) & 1023];
            cc[j][0] = (cc[j][0] + b0) * 0.125f;
            cc[j][1] = (cc[j][1] + b1) * 0.125f;
            cc[j][2] = (cc[j][2] + b0) * 0.125f;
            cc[j][3] = (cc[j][3] + b1) * 0.125f;
            vmA = fmaxf(vmA, fmaxf(cc[j][0], cc[j][1]));
            vmB = fmaxf(vmB, fmaxf(cc[j][2], cc[j][3]));
        }
        vmA = fmaxf(vmA, __shfl_xor_sync(0xffffffffu, vmA, 1));
        vmA = fmaxf(vmA, __shfl_xor_sync(0xffffffffu, vmA, 2));
        vmB = fmaxf(vmB, __shfl_xor_sync(0xffffffffu, vmB, 1));
        vmB = fmaxf(vmB, __shfl_xor_sync(0xffffffffu, vmB, 2));

        float nmA = fmaxf(mA, vmA), nmB = fmaxf(mB, vmB);
        float fA = __expf(mA - nmA), fB = __expf(mB - nmB);
        mA = nmA; mB = nmB;
        #pragma unroll
        for (int t = 0; t < 2; t++) {
            o[t][0] *= fA; o[t][1] *= fA; o[t][2] *= fB; o[t][3] *= fB;
        }
        lA *= fA; lB *= fB;

        // ---- P = exp(S - m), pack fp16 A-fragments, accumulate l ----
        float sA = 0.f, sB = 0.f;
        uint32_t pa[16], pb[16];
        #pragma unroll
        for (int j = 0; j < 16; j++) {
            float p0 = __expf(cc[j][0] - nmA), p1 = __expf(cc[j][1] - nmA);
            float p2 = __expf(cc[j][2] - nmB), p3 = __expf(cc[j][3] - nmB);
            sA += p0 + p1; sB += p2 + p3;
            __half2 hA = __floats2half2_rn(p0, p1);
            __half2 hB = __floats2half2_rn(p2, p3);
            pa[j] = *(uint32_t*)&hA;
            pb[j] = *(uint32_t*)&hB;
        }
        sA += __shfl_xor_sync(0xffffffffu, sA, 1);
        sA += __shfl_xor_sync(0xffffffffu, sA, 2);
        sB += __shfl_xor_sync(0xffffffffu, sB, 1);
        sB += __shfl_xor_sync(0xffffffffu, sB, 2);
        lA += sA; lB += sB;

        // ---- O += P @ Wv_chunk^T ----
        #pragma unroll
        for (int kk2 = 0; kk2 < 8; kk2++) {
            uint32_t a[4] = { pa[2 * kk2], pb[2 * kk2], pa[2 * kk2 + 1], pb[2 * kk2 + 1] };
            #pragma unroll
            for (int t = 0; t < 2; t++) {
                int n = t * 8 + qr;
                uint32_t b0 = *(const uint32_t*)&Wvs[n * 1032 + ch * 128 + kk2 * 16 + grp * 2];
                uint32_t b1 = *(const uint32_t*)&Wvs[n * 1032 + ch * 128 + kk2 * 16 + 8 + grp * 2];
                mma_f16(o[t], a, b0, b1);
            }
        }
        __syncthreads();   // protect Wks[ch&1] before next prefetch overwrites it
    }

    // ---- epilogue: normalize, +bv, write V16 (fp16) ----
    float iA = 1.f / lA, iB = 1.f / lB;
    int rowA = row0 + warp * 16 + qr;
    #pragma unroll
    for (int t = 0; t < 2; t++) {
        int v0 = t * 8 + grp * 2;
        float b0 = bv[v0], b1 = bv[v0 + 1];
        *(__half2*)&V16[(long)rowA * 16 + v0] =
            __floats2half2_rn(o[t][0] * iA + b0, o[t][1] * iA + b1);
        *(__half2*)&V16[(long)(rowA + 8) * 16 + v0] =
            __floats2half2_rn(o[t][2] * iB + b0, o[t][3] * iB + b1);
    }
}

// ---------------------------------------------------------------------------
extern "C" void kernel_launch(void* const* d_in, const int* in_sizes, int n_in,
                              void* d_out, int out_size)
{
    const float* x  = (const float*)d_in[0];
    const float* Wq = (const float*)d_in[1];
    const float* bq = (const float*)d_in[2];
    const float* Wk = (const float*)d_in[3];
    const float* bk = (const float*)d_in[4];
    const float* Wv = (const float*)d_in[5];
    const float* bv = (const float*)d_in[6];
    const float* Wh = (const float*)d_in[7];
    const float* bh = (const float*)d_in[8];
    float* out = (float*)d_out;

    __half *x16, *Wq16, *Wk16, *Wv16, *Wh16, *Q16, *V16;
    cudaGetSymbolAddress((void**)&x16,  g_x16);
    cudaGetSymbolAddress((void**)&Wq16, g_Wq16);
    cudaGetSymbolAddress((void**)&Wk16, g_Wk16);
    cudaGetSymbolAddress((void**)&Wv16, g_Wv16);
    cudaGetSymbolAddress((void**)&Wh16, g_Wh16);
    cudaGetSymbolAddress((void**)&Q16,  g_Q16);
    cudaGetSymbolAddress((void**)&V16,  g_V16);

    cudaFuncSetAttribute(attn_flash, cudaFuncAttributeMaxDynamicSharedMemorySize,
                         ATT_SMEM_BYTES);
    cudaFuncSetAttribute(hgemm_nt<true>, cudaFuncAttributeMaxDynamicSharedMemorySize,
                         G_SMEM);
    cudaFuncSetAttribute(hgemm_nt<false>, cudaFuncAttributeMaxDynamicSharedMemorySize,
                         G_SMEM);

    // fp32 -> fp16 conversion (single fused launch)
    cvt_all<<<(1069056 + 255) / 256, 256>>>(
        (const float4*)x, (const float4*)Wq, (const float4*)Wk,
        (const float4*)Wv, (const float4*)Wh,
        (__half2*)x16, (__half2*)Wq16, (__half2*)Wk16,
        (__half2*)Wv16, (__half2*)Wh16);

    // Stage 1: Q16 = x16 @ Wq16^T + bq   (2048 x 1024 x 1024, fp16 out)
    hgemm_nt<true><<<dim3(8, 16, 1), 256, G_SMEM>>>(
        x16, 0, 1024, Wq16, bq, Q16, 0, 1024, 2048);

    // Stage 2: flash attention over all 32768 (pos,head) rows -> V16 (32768 x 16)
    attn_flash<<<256, 256, ATT_SMEM_BYTES>>>(Q16, Wk16, bk, Wv16, bv, V16);

    // Stage 3: out[b,w,:] = V16[b, w*256 : +1024] @ Wh16^T + bh  (lda=256 overlap)
    hgemm_nt<false><<<dim3(8, 8, 2), 256, G_SMEM>>>(
        V16, 262144, 256, Wh16, bh, out, 1021L * 1024, 1024, 1021);
}

// round 7
// speedup vs baseline: 7.8575x; 1.0248x over previous
#include <cuda_runtime.h>
#include <cuda_fp16.h>
#include <cstdint>

// D=1024, H=16, M=1024, K=4, ST=1, HD=64, VD=16
// Pipeline (all tensor-core fp16 mma.sync, fp32 accum):
//   Q = x @ Wq^T + bq                         (2048 x 1024 x 1024)
//   flash: S = Qh @ Wk^T (+bk)/8 ; att=softmax ; V = att @ Wv^T + bv  (32768x16)
//   out[b,w,:] = V[b, w*256 : +1024] @ Wh^T + bh   (overlap => lda=256)

__device__ __half g_x16 [2048 * 1024];
__device__ __half g_Wq16[1024 * 1024];
__device__ __half g_Wk16[1024 * 64];
__device__ __half g_Wv16[16 * 1024];
__device__ __half g_Wh16[1024 * 1024];
__device__ __half g_Q16 [2048 * 1024];
__device__ __half g_V16 [2048 * 256 + 2048];   // +pad: stage-3 tail rows overrun

// ---------------------------------------------------------------------------
__device__ __forceinline__ void cp_async16(void* smem, const void* gmem)
{
    uint32_t s = (uint32_t)__cvta_generic_to_shared(smem);
    asm volatile("cp.async.cg.shared.global [%0], [%1], 16;\n" :: "r"(s), "l"(gmem));
}
__device__ __forceinline__ void cp_commit()
{
    asm volatile("cp.async.commit_group;\n");
}
template <int N>
__device__ __forceinline__ void cp_wait()
{
    asm volatile("cp.async.wait_group %0;\n" :: "n"(N));
}

__device__ __forceinline__ void ldsm_x4(uint32_t& r0, uint32_t& r1, uint32_t& r2,
                                        uint32_t& r3, uint32_t addr)
{
    asm volatile("ldmatrix.sync.aligned.m8n8.x4.shared.b16 {%0,%1,%2,%3}, [%4];"
                 : "=r"(r0), "=r"(r1), "=r"(r2), "=r"(r3) : "r"(addr));
}

__device__ __forceinline__ void mma_f16(float* c, const uint32_t* a, uint32_t b0, uint32_t b1)
{
    asm volatile(
        "mma.sync.aligned.m16n8k16.row.col.f32.f16.f16.f32 "
        "{%0,%1,%2,%3}, {%4,%5,%6,%7}, {%8,%9}, {%0,%1,%2,%3};\n"
        : "+f"(c[0]), "+f"(c[1]), "+f"(c[2]), "+f"(c[3])
        : "r"(a[0]), "r"(a[1]), "r"(a[2]), "r"(a[3]), "r"(b0), "r"(b1));
}

// ---------------------------------------------------------------------------
// Fused fp32 -> fp16 conversion for all 5 tensors in ONE launch.
// ---------------------------------------------------------------------------
__global__ __launch_bounds__(256)
void cvt_all(const float4* __restrict__ x,  const float4* __restrict__ wq,
             const float4* __restrict__ wk, const float4* __restrict__ wv,
             const float4* __restrict__ wh,
             __half2* ox, __half2* owq, __half2* owk, __half2* owv, __half2* owh)
{
    int i = blockIdx.x * blockDim.x + threadIdx.x;
    const float4* in;
    __half2* out;
    int off;
    if      (i <  524288) { in = x;  out = ox;  off = i; }
    else if (i <  786432) { in = wq; out = owq; off = i - 524288; }
    else if (i <  802816) { in = wk; out = owk; off = i - 786432; }
    else if (i <  806912) { in = wv; out = owv; off = i - 802816; }
    else if (i < 1069056) { in = wh; out = owh; off = i - 806912; }
    else return;
    float4 v = in[off];
    out[2 * off]     = __floats2half2_rn(v.x, v.y);
    out[2 * off + 1] = __floats2half2_rn(v.z, v.w);
}

// ---------------------------------------------------------------------------
// HGEMM NT: C[r][c] = sum_k A[r][k]*B[c][k] + bias[c]
// BM=128, BN=64, BK=64, K=1024 (16 chunks). 256 threads, 8 warps (4x2 grid,
// warp tile 32x32). 3-stage cp.async ring, one __syncthreads per chunk,
// ldmatrix fragment loads. 2 CTAs/SM.
// smem/stage: A[128][72] (18432 B) + B[64][72] (9216 B) = 27648 B; x3 = 82944 B.
// ---------------------------------------------------------------------------
#define G_STAGE 27648
#define G_SMEM  (3 * G_STAGE)

template <bool HALF_OUT>
__global__ __launch_bounds__(256, 2)
void hgemm_nt(const __half* __restrict__ A, long aBatch, int lda,
              const __half* __restrict__ B,
              const float* __restrict__ bias,
              void* __restrict__ Cv, long cBatch, int ldc, int M)
{
    extern __shared__ char sm[];
    const uint32_t smem_u = (uint32_t)__cvta_generic_to_shared(sm);

    const int tid = threadIdx.x;
    const int warp = tid >> 5, lane = tid & 31;
    const int qr = lane >> 2, grp = lane & 3;
    const int wr = (warp & 3) * 32;         // warp row in tile (0..96)
    const int wc = (warp >> 2) * 32;        // warp col in tile (0 or 32)
    const int row0 = blockIdx.y * 128;
    const int col0 = blockIdx.x * 64;

    const __half* Ab = A + (long)blockIdx.z * aBatch;
    const __half* Bb = B + (long)col0 * 1024;

    // cp.async slots: A 4 x 16B/thread (128 rows x 64 halves), B 2 x 16B/thread
    uint32_t sA[4], sB[2];
    long aoff[4], boff[2];
    #pragma unroll
    for (int i = 0; i < 4; i++) {
        int u = tid + 256 * i;
        int r = u >> 3, c8 = (u & 7) * 8;
        sA[i] = r * 144 + c8 * 2;
        aoff[i] = (long)(row0 + r) * lda + c8;
    }
    #pragma unroll
    for (int i = 0; i < 2; i++) {
        int u = tid + 256 * i;
        int r = u >> 3, c8 = (u & 7) * 8;
        sB[i] = 18432 + r * 144 + c8 * 2;
        boff[i] = (long)r * 1024 + c8;
    }

    auto load_chunk = [&](int ch) {
        char* base = sm + (ch % 3) * G_STAGE;
        const int k0 = ch * 64;
        #pragma unroll
        for (int i = 0; i < 4; i++) cp_async16(base + sA[i], Ab + aoff[i] + k0);
        #pragma unroll
        for (int i = 0; i < 2; i++) cp_async16(base + sB[i], Bb + boff[i] + k0);
        cp_commit();
    };

    // ldmatrix lane base offsets (bytes within stage)
    const uint32_t aLane = (uint32_t)((wr + (lane & 7) + ((lane >> 3) & 1) * 8) * 144
                                      + (lane >> 4) * 16);
    const uint32_t bLane = (uint32_t)(18432 + (wc + (lane & 7) + (lane >> 4) * 8) * 144
                                      + ((lane >> 3) & 1) * 16);

    float acc[2][4][4] = {};

    load_chunk(0);
    load_chunk(1);

    for (int ch = 0; ch < 16; ch++) {
        if (ch < 15) cp_wait<1>(); else cp_wait<0>();
        __syncthreads();
        if (ch + 2 < 16) load_chunk(ch + 2);

        const uint32_t sb = smem_u + (ch % 3) * G_STAGE;
        const uint32_t aAdr = sb + aLane;
        const uint32_t bAdr = sb + bLane;

        #pragma unroll
        for (int kk = 0; kk < 4; kk++) {
            uint32_t a0[4], a1[4];
            ldsm_x4(a0[0], a0[1], a0[2], a0[3], aAdr + kk * 32);
            ldsm_x4(a1[0], a1[1], a1[2], a1[3], aAdr + kk * 32 + 16 * 144);
            #pragma unroll
            for (int pj = 0; pj < 2; pj++) {
                uint32_t q[4];
                ldsm_x4(q[0], q[1], q[2], q[3], bAdr + kk * 32 + pj * 16 * 144);
                mma_f16(acc[0][2 * pj],     a0, q[0], q[1]);
                mma_f16(acc[0][2 * pj + 1], a0, q[2], q[3]);
                mma_f16(acc[1][2 * pj],     a1, q[0], q[1]);
                mma_f16(acc[1][2 * pj + 1], a1, q[2], q[3]);
            }
        }
    }

    // epilogue
    #pragma unroll
    for (int mi = 0; mi < 2; mi++) {
        #pragma unroll
        for (int nj = 0; nj < 4; nj++) {
            float* c = acc[mi][nj];
            int col = col0 + wc + nj * 8 + grp * 2;
            float b0 = bias[col], b1 = bias[col + 1];
            int rA = row0 + wr + mi * 16 + qr;
            int rB = rA + 8;
            if (HALF_OUT) {
                __half* C = (__half*)Cv + (long)blockIdx.z * cBatch;
                if (rA < M) *(__half2*)&C[(long)rA * ldc + col] = __floats2half2_rn(c[0] + b0, c[1] + b1);
                if (rB < M) *(__half2*)&C[(long)rB * ldc + col] = __floats2half2_rn(c[2] + b0, c[3] + b1);
            } else {
                float* C = (float*)Cv + (long)blockIdx.z * cBatch;
                if (rA < M) *(float2*)&C[(long)rA * ldc + col] = make_float2(c[0] + b0, c[1] + b1);
                if (rB < M) *(float2*)&C[(long)rB * ldc + col] = make_float2(c[2] + b0, c[3] + b1);
            }
        }
    }
}

// ---------------------------------------------------------------------------
// Flash attention: rows = Qh (32768 x 64), K = Wk (1024 x 64), V = Wv^T (1024 x 16)
// 128 rows/CTA (256 CTAs), 8 warps x 16 rows, online softmax over 8 m-chunks of 128.
// ---------------------------------------------------------------------------
#define ATT_SMEM_BYTES (128 * 72 * 2 + 2 * 128 * 72 * 2 + 16 * 1032 * 2 + 1024 * 4)

__global__ __launch_bounds__(256)
void attn_flash(const __half* __restrict__ Q16, const __half* __restrict__ Wk16,
                const float* __restrict__ bk, const __half* __restrict__ Wv16,
                const float* __restrict__ bv, __half* __restrict__ V16)
{
    extern __shared__ char smraw[];
    __half* Qs  = (__half*)smraw;               // [128][72]
    __half* Wks = Qs + 128 * 72;                // [2][128][72]
    __half* Wvs = Wks + 2 * 128 * 72;           // [16][1032]
    float*  bks = (float*)(Wvs + 16 * 1032);    // [1024]

    const uint32_t smem_u = (uint32_t)__cvta_generic_to_shared(smraw);
    const int tid = threadIdx.x;
    const int warp = tid >> 5, lane = tid & 31;
    const int qr = lane >> 2, grp = lane & 3;
    const int row0 = blockIdx.x * 128;

    #pragma unroll
    for (int i = 0; i < 4; i++) {
        int v = tid + 256 * i;
        cp_async16(&Wks[(v >> 3) * 72 + (v & 7) * 8],
                   &Wk16[(long)(v >> 3) * 64 + (v & 7) * 8]);
    }
    cp_commit();

    #pragma unroll
    for (int i = 0; i < 4; i++) {
        int v = tid + 256 * i;
        *(float4*)&Qs[(v >> 3) * 72 + (v & 7) * 8] =
            *(const float4*)&Q16[(long)(row0 + (v >> 3)) * 64 + (v & 7) * 8];
    }
    #pragma unroll
    for (int i = 0; i < 8; i++) {
        int v = tid + 256 * i;
        int r = v >> 7, c = v & 127;
        *(float4*)&Wvs[r * 1032 + c * 8] = *(const float4*)&Wv16[r * 1024 + c * 8];
    }
    ((float4*)bks)[tid] = ((const float4*)bk)[tid];

    const uint32_t qAdr = smem_u
        + (uint32_t)((warp * 16 + (lane & 7) + ((lane >> 3) & 1) * 8) * 144
                     + (lane >> 4) * 16);
    const uint32_t wkLane = (uint32_t)(128 * 144
        + ((lane & 7) + (lane >> 4) * 8) * 144 + ((lane >> 3) & 1) * 16);

    const float NEG_INF = -1e30f;
    float mA = NEG_INF, mB = NEG_INF, lA = 0.f, lB = 0.f;
    float o[2][4] = {};

    for (int ch = 0; ch < 8; ch++) {
        if (ch < 7) {
            __half* Wkn = Wks + ((ch + 1) & 1) * 128 * 72;
            #pragma unroll
            for (int i = 0; i < 4; i++) {
                int v = tid + 256 * i;
                cp_async16(&Wkn[(v >> 3) * 72 + (v & 7) * 8],
                           &Wk16[(long)((ch + 1) * 128 + (v >> 3)) * 64 + (v & 7) * 8]);
            }
            cp_commit();
            cp_wait<1>();
        } else {
            cp_wait<0>();
        }
        __syncthreads();

        const uint32_t wkAdr = smem_u + wkLane + (uint32_t)((ch & 1) * 128 * 144);

        float cc[16][4] = {};
        #pragma unroll
        for (int kk = 0; kk < 4; kk++) {
            uint32_t a[4];
            ldsm_x4(a[0], a[1], a[2], a[3], qAdr + kk * 32);
            #pragma unroll
            for (int pj = 0; pj < 8; pj++) {
                uint32_t q[4];
                ldsm_x4(q[0], q[1], q[2], q[3], wkAdr + kk * 32 + pj * 16 * 144);
                mma_f16(cc[2 * pj],     a, q[0], q[1]);
                mma_f16(cc[2 * pj + 1], a, q[2], q[3]);
            }
        }

        float vmA = NEG_INF, vmB = NEG_INF;
        #pragma unroll
        for (int j = 0; j < 16; j++) {
            int m = ch * 128 + j * 8 + grp * 2;
            float b0 = bks[m & 1023], b1 = bks[(m + 1) & 1023];
            cc[j][0] = (cc[j][0] + b0) * 0.125f;
            cc[j][1] = (cc[j][1] + b1) * 0.125f;
            cc[j][2] = (cc[j][2] + b0) * 0.125f;
            cc[j][3] = (cc[j][3] + b1) * 0.125f;
            vmA = fmaxf(vmA, fmaxf(cc[j][0], cc[j][1]));
            vmB = fmaxf(vmB, fmaxf(cc[j][2], cc[j][3]));
        }
        vmA = fmaxf(vmA, __shfl_xor_sync(0xffffffffu, vmA, 1));
        vmA = fmaxf(vmA, __shfl_xor_sync(0xffffffffu, vmA, 2));
        vmB = fmaxf(vmB, __shfl_xor_sync(0xffffffffu, vmB, 1));
        vmB = fmaxf(vmB, __shfl_xor_sync(0xffffffffu, vmB, 2));

        float nmA = fmaxf(mA, vmA), nmB = fmaxf(mB, vmB);
        float fA = __expf(mA - nmA), fB = __expf(mB - nmB);
        mA = nmA; mB = nmB;
        #pragma unroll
        for (int t = 0; t < 2; t++) {
            o[t][0] *= fA; o[t][1] *= fA; o[t][2] *= fB; o[t][3] *= fB;
        }
        lA *= fA; lB *= fB;

        float sA = 0.f, sB = 0.f;
        uint32_t pa[16], pb[16];
        #pragma unroll
        for (int j = 0; j < 16; j++) {
            float p0 = __expf(cc[j][0] - nmA), p1 = __expf(cc[j][1] - nmA);
            float p2 = __expf(cc[j][2] - nmB), p3 = __expf(cc[j][3] - nmB);
            sA += p0 + p1; sB += p2 + p3;
            __half2 hA = __floats2half2_rn(p0, p1);
            __half2 hB = __floats2half2_rn(p2, p3);
            pa[j] = *(uint32_t*)&hA;
            pb[j] = *(uint32_t*)&hB;
        }
        sA += __shfl_xor_sync(0xffffffffu, sA, 1);
        sA += __shfl_xor_sync(0xffffffffu, sA, 2);
        sB += __shfl_xor_sync(0xffffffffu, sB, 1);
        sB += __shfl_xor_sync(0xffffffffu, sB, 2);
        lA += sA; lB += sB;

        #pragma unroll
        for (int kk2 = 0; kk2 < 8; kk2++) {
            uint32_t a[4] = { pa[2 * kk2], pb[2 * kk2], pa[2 * kk2 + 1], pb[2 * kk2 + 1] };
            #pragma unroll
            for (int t = 0; t < 2; t++) {
                int n = t * 8 + qr;
                uint32_t b0 = *(const uint32_t*)&Wvs[n * 1032 + ch * 128 + kk2 * 16 + grp * 2];
                uint32_t b1 = *(const uint32_t*)&Wvs[n * 1032 + ch * 128 + kk2 * 16 + 8 + grp * 2];
                mma_f16(o[t], a, b0, b1);
            }
        }
        __syncthreads();
    }

    float iA = 1.f / lA, iB = 1.f / lB;
    int rowA = row0 + warp * 16 + qr;
    #pragma unroll
    for (int t = 0; t < 2; t++) {
        int v0 = t * 8 + grp * 2;
        float b0 = bv[v0], b1 = bv[v0 + 1];
        *(__half2*)&V16[(long)rowA * 16 + v0] =
            __floats2half2_rn(o[t][0] * iA + b0, o[t][1] * iA + b1);
        *(__half2*)&V16[(long)(rowA + 8) * 16 + v0] =
            __floats2half2_rn(o[t][2] * iB + b0, o[t][3] * iB + b1);
    }
}

// ---------------------------------------------------------------------------
extern "C" void kernel_launch(void* const* d_in, const int* in_sizes, int n_in,
                              void* d_out, int out_size)
{
    const float* x  = (const float*)d_in[0];
    const float* Wq = (const float*)d_in[1];
    const float* bq = (const float*)d_in[2];
    const float* Wk = (const float*)d_in[3];
    const float* bk = (const float*)d_in[4];
    const float* Wv = (const float*)d_in[5];
    const float* bv = (const float*)d_in[6];
    const float* Wh = (const float*)d_in[7];
    const float* bh = (const float*)d_in[8];
    float* out = (float*)d_out;

    __half *x16, *Wq16, *Wk16, *Wv16, *Wh16, *Q16, *V16;
    cudaGetSymbolAddress((void**)&x16,  g_x16);
    cudaGetSymbolAddress((void**)&Wq16, g_Wq16);
    cudaGetSymbolAddress((void**)&Wk16, g_Wk16);
    cudaGetSymbolAddress((void**)&Wv16, g_Wv16);
    cudaGetSymbolAddress((void**)&Wh16, g_Wh16);
    cudaGetSymbolAddress((void**)&Q16,  g_Q16);
    cudaGetSymbolAddress((void**)&V16,  g_V16);

    cudaFuncSetAttribute(attn_flash, cudaFuncAttributeMaxDynamicSharedMemorySize,
                         ATT_SMEM_BYTES);
    cudaFuncSetAttribute(hgemm_nt<true>, cudaFuncAttributeMaxDynamicSharedMemorySize,
                         G_SMEM);
    cudaFuncSetAttribute(hgemm_nt<false>, cudaFuncAttributeMaxDynamicSharedMemorySize,
                         G_SMEM);

    // fp32 -> fp16 conversion (single fused launch)
    cvt_all<<<(1069056 + 255) / 256, 256>>>(
        (const float4*)x, (const float4*)Wq, (const float4*)Wk,
        (const float4*)Wv, (const float4*)Wh,
        (__half2*)x16, (__half2*)Wq16, (__half2*)Wk16,
        (__half2*)Wv16, (__half2*)Wh16);

    // Stage 1: Q16 = x16 @ Wq16^T + bq   (2048 x 1024 x 1024, fp16 out)
    hgemm_nt<true><<<dim3(16, 16, 1), 256, G_SMEM>>>(
        x16, 0, 1024, Wq16, bq, Q16, 0, 1024, 2048);

    // Stage 2: flash attention over all 32768 (pos,head) rows -> V16 (32768 x 16)
    attn_flash<<<256, 256, ATT_SMEM_BYTES>>>(Q16, Wk16, bk, Wv16, bv, V16);

    // Stage 3: out[b,w,:] = V16[b, w*256 : +1024] @ Wh16^T + bh  (lda=256 overlap)
    hgemm_nt<false><<<dim3(16, 8, 2), 256, G_SMEM>>>(
        V16, 262144, 256, Wh16, bh, out, 1021L * 1024, 1024, 1021);
}

// round 8
// speedup vs baseline: 8.2090x; 1.0447x over previous
#include <cuda_runtime.h>
#include <cuda_fp16.h>
#include <cstdint>

// D=1024, H=16, M=1024, K=4, ST=1, HD=64, VD=16
// Pipeline (all tensor-core fp16 mma.sync, fp32 accum):
//   Q = x @ Wq^T + bq                         (2048 x 1024 x 1024)
//   flash: S = Qh @ Wk^T (+bk)/8 ; att=softmax ; V = att @ Wv^T + bv  (32768x16)
//   out[b,w,:] = V[b, w*256 : +1024] @ Wh^T + bh   (overlap => lda=256)

__device__ __half g_x16 [2048 * 1024];
__device__ __half g_Wq16[1024 * 1024];
__device__ __half g_Wk16[1024 * 64];
__device__ __half g_Wv16[16 * 1024];
__device__ __half g_Wh16[1024 * 1024];
__device__ __half g_Q16 [2048 * 1024];
__device__ __half g_V16 [2048 * 256 + 2048];   // +pad: stage-3 tail rows overrun

// ---------------------------------------------------------------------------
__device__ __forceinline__ void cp_async16(void* smem, const void* gmem)
{
    uint32_t s = (uint32_t)__cvta_generic_to_shared(smem);
    asm volatile("cp.async.cg.shared.global [%0], [%1], 16;\n" :: "r"(s), "l"(gmem));
}
__device__ __forceinline__ void cp_commit()
{
    asm volatile("cp.async.commit_group;\n");
}
template <int N>
__device__ __forceinline__ void cp_wait()
{
    asm volatile("cp.async.wait_group %0;\n" :: "n"(N));
}

__device__ __forceinline__ void ldsm_x4(uint32_t* r, uint32_t addr)
{
    asm volatile("ldmatrix.sync.aligned.m8n8.x4.shared.b16 {%0,%1,%2,%3}, [%4];"
                 : "=r"(r[0]), "=r"(r[1]), "=r"(r[2]), "=r"(r[3]) : "r"(addr));
}

__device__ __forceinline__ void mma_f16(float* c, const uint32_t* a, uint32_t b0, uint32_t b1)
{
    asm volatile(
        "mma.sync.aligned.m16n8k16.row.col.f32.f16.f16.f32 "
        "{%0,%1,%2,%3}, {%4,%5,%6,%7}, {%8,%9}, {%0,%1,%2,%3};\n"
        : "+f"(c[0]), "+f"(c[1]), "+f"(c[2]), "+f"(c[3])
        : "r"(a[0]), "r"(a[1]), "r"(a[2]), "r"(a[3]), "r"(b0), "r"(b1));
}

// ---------------------------------------------------------------------------
// Fused fp32 -> fp16 conversion for all 5 tensors in ONE launch.
// ---------------------------------------------------------------------------
__global__ __launch_bounds__(256)
void cvt_all(const float4* __restrict__ x,  const float4* __restrict__ wq,
             const float4* __restrict__ wk, const float4* __restrict__ wv,
             const float4* __restrict__ wh,
             __half2* ox, __half2* owq, __half2* owk, __half2* owv, __half2* owh)
{
    int i = blockIdx.x * blockDim.x + threadIdx.x;
    const float4* in;
    __half2* out;
    int off;
    if      (i <  524288) { in = x;  out = ox;  off = i; }
    else if (i <  786432) { in = wq; out = owq; off = i - 524288; }
    else if (i <  802816) { in = wk; out = owk; off = i - 786432; }
    else if (i <  806912) { in = wv; out = owv; off = i - 802816; }
    else if (i < 1069056) { in = wh; out = owh; off = i - 806912; }
    else return;
    float4 v = in[off];
    out[2 * off]     = __floats2half2_rn(v.x, v.y);
    out[2 * off + 1] = __floats2half2_rn(v.z, v.w);
}

// ---------------------------------------------------------------------------
// HGEMM NT: C[r][c] = sum_k A[r][k]*B[c][k] + bias[c]
// BM=128, BN=64, BK=64, K=1024 (16 chunks). 256 threads, 8 warps (4x2 grid,
// warp tile 32x32). 3-stage cp.async ring, one __syncthreads per chunk,
// ldmatrix fragments double-buffered across k16 steps. 2 CTAs/SM.
// ---------------------------------------------------------------------------
#define G_STAGE 27648
#define G_SMEM  (3 * G_STAGE)

template <bool HALF_OUT>
__global__ __launch_bounds__(256, 2)
void hgemm_nt(const __half* __restrict__ A, long aBatch, int lda,
              const __half* __restrict__ B,
              const float* __restrict__ bias,
              void* __restrict__ Cv, long cBatch, int ldc, int M)
{
    extern __shared__ char sm[];
    const uint32_t smem_u = (uint32_t)__cvta_generic_to_shared(sm);

    const int tid = threadIdx.x;
    const int warp = tid >> 5, lane = tid & 31;
    const int qr = lane >> 2, grp = lane & 3;
    const int wr = (warp & 3) * 32;
    const int wc = (warp >> 2) * 32;
    const int row0 = blockIdx.y * 128;
    const int col0 = blockIdx.x * 64;

    const __half* Ab = A + (long)blockIdx.z * aBatch;
    const __half* Bb = B + (long)col0 * 1024;

    uint32_t sAo[4], sBo[2];
    long aoff[4], boff[2];
    #pragma unroll
    for (int i = 0; i < 4; i++) {
        int u = tid + 256 * i;
        int r = u >> 3, c8 = (u & 7) * 8;
        sAo[i] = r * 144 + c8 * 2;
        aoff[i] = (long)(row0 + r) * lda + c8;
    }
    #pragma unroll
    for (int i = 0; i < 2; i++) {
        int u = tid + 256 * i;
        int r = u >> 3, c8 = (u & 7) * 8;
        sBo[i] = 18432 + r * 144 + c8 * 2;
        boff[i] = (long)r * 1024 + c8;
    }

    auto load_chunk = [&](int ch) {
        char* base = sm + (ch % 3) * G_STAGE;
        const int k0 = ch * 64;
        #pragma unroll
        for (int i = 0; i < 4; i++) cp_async16(base + sAo[i], Ab + aoff[i] + k0);
        #pragma unroll
        for (int i = 0; i < 2; i++) cp_async16(base + sBo[i], Bb + boff[i] + k0);
        cp_commit();
    };

    const uint32_t aLane = (uint32_t)((wr + (lane & 7) + ((lane >> 3) & 1) * 8) * 144
                                      + (lane >> 4) * 16);
    const uint32_t bLane = (uint32_t)(18432 + (wc + (lane & 7) + (lane >> 4) * 8) * 144
                                      + ((lane >> 3) & 1) * 16);

    float acc[2][4][4] = {};

    load_chunk(0);
    load_chunk(1);

    for (int ch = 0; ch < 16; ch++) {
        if (ch < 15) cp_wait<1>(); else cp_wait<0>();
        __syncthreads();
        if (ch + 2 < 16) load_chunk(ch + 2);

        const uint32_t sb = smem_u + (ch % 3) * G_STAGE;
        const uint32_t aAdr = sb + aLane;
        const uint32_t bAdr = sb + bLane;

        // fragment double-buffer across kk
        uint32_t af[2][8], bf[2][8];
        ldsm_x4(&af[0][0], aAdr);
        ldsm_x4(&af[0][4], aAdr + 16 * 144);
        ldsm_x4(&bf[0][0], bAdr);
        ldsm_x4(&bf[0][4], bAdr + 16 * 144);

        #pragma unroll
        for (int kk = 0; kk < 4; kk++) {
            const int cur = kk & 1, nxt = cur ^ 1;
            if (kk < 3) {
                ldsm_x4(&af[nxt][0], aAdr + (kk + 1) * 32);
                ldsm_x4(&af[nxt][4], aAdr + (kk + 1) * 32 + 16 * 144);
                ldsm_x4(&bf[nxt][0], bAdr + (kk + 1) * 32);
                ldsm_x4(&bf[nxt][4], bAdr + (kk + 1) * 32 + 16 * 144);
            }
            #pragma unroll
            for (int pj = 0; pj < 2; pj++) {
                const uint32_t* q = &bf[cur][pj * 4];
                mma_f16(acc[0][2 * pj],     &af[cur][0], q[0], q[1]);
                mma_f16(acc[0][2 * pj + 1], &af[cur][0], q[2], q[3]);
                mma_f16(acc[1][2 * pj],     &af[cur][4], q[0], q[1]);
                mma_f16(acc[1][2 * pj + 1], &af[cur][4], q[2], q[3]);
            }
        }
    }

    // epilogue
    #pragma unroll
    for (int mi = 0; mi < 2; mi++) {
        #pragma unroll
        for (int nj = 0; nj < 4; nj++) {
            float* c = acc[mi][nj];
            int col = col0 + wc + nj * 8 + grp * 2;
            float b0 = bias[col], b1 = bias[col + 1];
            int rA = row0 + wr + mi * 16 + qr;
            int rB = rA + 8;
            if (HALF_OUT) {
                __half* C = (__half*)Cv + (long)blockIdx.z * cBatch;
                if (rA < M) *(__half2*)&C[(long)rA * ldc + col] = __floats2half2_rn(c[0] + b0, c[1] + b1);
                if (rB < M) *(__half2*)&C[(long)rB * ldc + col] = __floats2half2_rn(c[2] + b0, c[3] + b1);
            } else {
                float* C = (float*)Cv + (long)blockIdx.z * cBatch;
                if (rA < M) *(float2*)&C[(long)rA * ldc + col] = make_float2(c[0] + b0, c[1] + b1);
                if (rB < M) *(float2*)&C[(long)rB * ldc + col] = make_float2(c[2] + b0, c[3] + b1);
            }
        }
    }
}

// ---------------------------------------------------------------------------
// Flash attention: rows = Qh (32768 x 64), K = Wk (1024 x 64), V = Wv^T (1024 x 16)
// 128 rows/CTA (256 CTAs), 8 warps x 16 rows, online softmax over 8 m-chunks of 128.
// Wk: 3-buffer cp.async ring, single __syncthreads per chunk.
// smem (halves): Qs[128*72] | Wks[3][128*72] | Wvs[16*1032] | bks f32[1024]
// ---------------------------------------------------------------------------
#define ATT_SMEM_BYTES (4 * 128 * 72 * 2 + 16 * 1032 * 2 + 1024 * 4)

__global__ __launch_bounds__(256)
void attn_flash(const __half* __restrict__ Q16, const __half* __restrict__ Wk16,
                const float* __restrict__ bk, const __half* __restrict__ Wv16,
                const float* __restrict__ bv, __half* __restrict__ V16)
{
    extern __shared__ char smraw[];
    __half* Qs  = (__half*)smraw;               // [128][72]
    __half* Wks = Qs + 128 * 72;                // [3][128][72]
    __half* Wvs = Wks + 3 * 128 * 72;           // [16][1032]
    float*  bks = (float*)(Wvs + 16 * 1032);    // [1024]

    const uint32_t smem_u = (uint32_t)__cvta_generic_to_shared(smraw);
    const int tid = threadIdx.x;
    const int warp = tid >> 5, lane = tid & 31;
    const int qr = lane >> 2, grp = lane & 3;
    const int row0 = blockIdx.x * 128;

    // prologue: Wk chunk 0 -> buffer 0
    #pragma unroll
    for (int i = 0; i < 4; i++) {
        int v = tid + 256 * i;
        cp_async16(&Wks[(v >> 3) * 72 + (v & 7) * 8],
                   &Wk16[(long)(v >> 3) * 64 + (v & 7) * 8]);
    }
    cp_commit();

    #pragma unroll
    for (int i = 0; i < 4; i++) {
        int v = tid + 256 * i;
        *(float4*)&Qs[(v >> 3) * 72 + (v & 7) * 8] =
            *(const float4*)&Q16[(long)(row0 + (v >> 3)) * 64 + (v & 7) * 8];
    }
    #pragma unroll
    for (int i = 0; i < 8; i++) {
        int v = tid + 256 * i;
        int r = v >> 7, c = v & 127;
        *(float4*)&Wvs[r * 1032 + c * 8] = *(const float4*)&Wv16[r * 1024 + c * 8];
    }
    ((float4*)bks)[tid] = ((const float4*)bk)[tid];

    // ldmatrix lane addresses
    const uint32_t qAdr = smem_u
        + (uint32_t)((warp * 16 + (lane & 7) + ((lane >> 3) & 1) * 8) * 144
                     + (lane >> 4) * 16);
    const uint32_t wkLane = (uint32_t)(128 * 144
        + ((lane & 7) + (lane >> 4) * 8) * 144 + ((lane >> 3) & 1) * 16);
    // Wvs ldsm: lanes 0-7: n=lane,k+0 | 8-15: n=lane-8,k+8 | 16-23: n8+,k+0 | 24-31: n8+,k+8
    const uint32_t vAdr = smem_u + (uint32_t)(4 * 128 * 144
        + ((lane & 7) + ((lane >> 4) & 1) * 8) * 2064 + ((lane >> 3) & 1) * 16);

    const float NEG_INF = -1e30f;
    float mA = NEG_INF, mB = NEG_INF, lA = 0.f, lB = 0.f;
    float o[2][4] = {};

    for (int ch = 0; ch < 8; ch++) {
        if (ch < 7) {
            __half* Wkn = Wks + ((ch + 1) % 3) * 128 * 72;
            #pragma unroll
            for (int i = 0; i < 4; i++) {
                int v = tid + 256 * i;
                cp_async16(&Wkn[(v >> 3) * 72 + (v & 7) * 8],
                           &Wk16[(long)((ch + 1) * 128 + (v >> 3)) * 64 + (v & 7) * 8]);
            }
            cp_commit();
            cp_wait<1>();
        } else {
            cp_wait<0>();
        }
        __syncthreads();

        const uint32_t wkAdr = smem_u + wkLane + (uint32_t)((ch % 3) * 128 * 144);

        // ---- S = Qtile @ Wk_chunk^T, B-fragments pipelined over pj ----
        float cc[16][4] = {};
        #pragma unroll
        for (int kk = 0; kk < 4; kk++) {
            uint32_t a[4];
            ldsm_x4(a, qAdr + kk * 32);
            uint32_t bf[2][4];
            ldsm_x4(bf[0], wkAdr + kk * 32);
            #pragma unroll
            for (int pj = 0; pj < 8; pj++) {
                if (pj < 7) ldsm_x4(bf[(pj + 1) & 1], wkAdr + kk * 32 + (pj + 1) * 16 * 144);
                const uint32_t* q = bf[pj & 1];
                mma_f16(cc[2 * pj],     a, q[0], q[1]);
                mma_f16(cc[2 * pj + 1], a, q[2], q[3]);
            }
        }

        // ---- bias + scale + row stats ----
        float vmA = NEG_INF, vmB = NEG_INF;
        #pragma unroll
        for (int j = 0; j < 16; j++) {
            int m = ch * 128 + j * 8 + grp * 2;
            float b0 = bks[m & 1023], b1 = bks[(m + 1) & 1023];
            cc[j][0] = (cc[j][0] + b0) * 0.125f;
            cc[j][1] = (cc[j][1] + b1) * 0.125f;
            cc[j][2] = (cc[j][2] + b0) * 0.125f;
            cc[j][3] = (cc[j][3] + b1) * 0.125f;
            vmA = fmaxf(vmA, fmaxf(cc[j][0], cc[j][1]));
            vmB = fmaxf(vmB, fmaxf(cc[j][2], cc[j][3]));
        }
        vmA = fmaxf(vmA, __shfl_xor_sync(0xffffffffu, vmA, 1));
        vmA = fmaxf(vmA, __shfl_xor_sync(0xffffffffu, vmA, 2));
        vmB = fmaxf(vmB, __shfl_xor_sync(0xffffffffu, vmB, 1));
        vmB = fmaxf(vmB, __shfl_xor_sync(0xffffffffu, vmB, 2));

        float nmA = fmaxf(mA, vmA), nmB = fmaxf(mB, vmB);
        float fA = __expf(mA - nmA), fB = __expf(mB - nmB);
        mA = nmA; mB = nmB;
        #pragma unroll
        for (int t = 0; t < 2; t++) {
            o[t][0] *= fA; o[t][1] *= fA; o[t][2] *= fB; o[t][3] *= fB;
        }
        lA *= fA; lB *= fB;

        // ---- fused: P = exp(S - m) pair-wise, immediate O += P @ Wv ----
        float sA = 0.f, sB = 0.f;
        #pragma unroll
        for (int kk2 = 0; kk2 < 8; kk2++) {
            uint32_t a[4];
            #pragma unroll
            for (int jj = 0; jj < 2; jj++) {
                int j = 2 * kk2 + jj;
                float p0 = __expf(cc[j][0] - nmA), p1 = __expf(cc[j][1] - nmA);
                float p2 = __expf(cc[j][2] - nmB), p3 = __expf(cc[j][3] - nmB);
                sA += p0 + p1; sB += p2 + p3;
                __half2 hA = __floats2half2_rn(p0, p1);
                __half2 hB = __floats2half2_rn(p2, p3);
                a[jj * 2]     = *(uint32_t*)&hA;
                a[jj * 2 + 1] = *(uint32_t*)&hB;
            }
            // reorder to A-fragment: {j0A, j0B, j1A, j1B} -> rows (qr, qr+8) x k16
            uint32_t af[4] = { a[0], a[1], a[2], a[3] };
            uint32_t q[4];
            ldsm_x4(q, vAdr + ch * 256 + kk2 * 32);
            mma_f16(o[0], af, q[0], q[1]);
            mma_f16(o[1], af, q[2], q[3]);
        }
        sA += __shfl_xor_sync(0xffffffffu, sA, 1);
        sA += __shfl_xor_sync(0xffffffffu, sA, 2);
        sB += __shfl_xor_sync(0xffffffffu, sB, 1);
        sB += __shfl_xor_sync(0xffffffffu, sB, 2);
        lA += sA; lB += sB;
    }

    // ---- epilogue: normalize, +bv, write V16 (fp16) ----
    float iA = 1.f / lA, iB = 1.f / lB;
    int rowA = row0 + warp * 16 + qr;
    #pragma unroll
    for (int t = 0; t < 2; t++) {
        int v0 = t * 8 + grp * 2;
        float b0 = bv[v0], b1 = bv[v0 + 1];
        *(__half2*)&V16[(long)rowA * 16 + v0] =
            __floats2half2_rn(o[t][0] * iA + b0, o[t][1] * iA + b1);
        *(__half2*)&V16[(long)(rowA + 8) * 16 + v0] =
            __floats2half2_rn(o[t][2] * iB + b0, o[t][3] * iB + b1);
    }
}

// ---------------------------------------------------------------------------
extern "C" void kernel_launch(void* const* d_in, const int* in_sizes, int n_in,
                              void* d_out, int out_size)
{
    const float* x  = (const float*)d_in[0];
    const float* Wq = (const float*)d_in[1];
    const float* bq = (const float*)d_in[2];
    const float* Wk = (const float*)d_in[3];
    const float* bk = (const float*)d_in[4];
    const float* Wv = (const float*)d_in[5];
    const float* bv = (const float*)d_in[6];
    const float* Wh = (const float*)d_in[7];
    const float* bh = (const float*)d_in[8];
    float* out = (float*)d_out;

    __half *x16, *Wq16, *Wk16, *Wv16, *Wh16, *Q16, *V16;
    cudaGetSymbolAddress((void**)&x16,  g_x16);
    cudaGetSymbolAddress((void**)&Wq16, g_Wq16);
    cudaGetSymbolAddress((void**)&Wk16, g_Wk16);
    cudaGetSymbolAddress((void**)&Wv16, g_Wv16);
    cudaGetSymbolAddress((void**)&Wh16, g_Wh16);
    cudaGetSymbolAddress((void**)&Q16,  g_Q16);
    cudaGetSymbolAddress((void**)&V16,  g_V16);

    cudaFuncSetAttribute(attn_flash, cudaFuncAttributeMaxDynamicSharedMemorySize,
                         ATT_SMEM_BYTES);
    cudaFuncSetAttribute(hgemm_nt<true>, cudaFuncAttributeMaxDynamicSharedMemorySize,
                         G_SMEM);
    cudaFuncSetAttribute(hgemm_nt<false>, cudaFuncAttributeMaxDynamicSharedMemorySize,
                         G_SMEM);

    // fp32 -> fp16 conversion (single fused launch)
    cvt_all<<<(1069056 + 255) / 256, 256>>>(
        (const float4*)x, (const float4*)Wq, (const float4*)Wk,
        (const float4*)Wv, (const float4*)Wh,
        (__half2*)x16, (__half2*)Wq16, (__half2*)Wk16,
        (__half2*)Wv16, (__half2*)Wh16);

    // Stage 1: Q16 = x16 @ Wq16^T + bq   (2048 x 1024 x 1024, fp16 out)
    hgemm_nt<true><<<dim3(16, 16, 1), 256, G_SMEM>>>(
        x16, 0, 1024, Wq16, bq, Q16, 0, 1024, 2048);

    // Stage 2: flash attention over all 32768 (pos,head) rows -> V16 (32768 x 16)
    attn_flash<<<256, 256, ATT_SMEM_BYTES>>>(Q16, Wk16, bk, Wv16, bv, V16);

    // Stage 3: out[b,w,:] = V16[b, w*256 : +1024] @ Wh16^T + bh  (lda=256 overlap)
    hgemm_nt<false><<<dim3(16, 8, 2), 256, G_SMEM>>>(
        V16, 262144, 256, Wh16, bh, out, 1021L * 1024, 1024, 1021);
}